// round 1
// baseline (speedup 1.0000x reference)
#include <cuda_runtime.h>

// Problem constants
constexpr int Bb_ = 4, S_ = 2048, D_ = 2048, H_ = 16, DH_ = 128;
constexpr int M_ = Bb_ * S_;  // 8192

// Scratch (static __device__ — no allocations allowed)
__device__ float g_Q[M_ * D_];
__device__ float g_K[M_ * D_];
__device__ float g_V[M_ * D_];
__device__ float g_Suf[M_ * D_];
__device__ float g_ctx[M_ * D_];
__device__ float g_csum[Bb_ * H_ * 32 * DH_];

#define DEV_INLINE __device__ __forceinline__

// Packed fp32x2 FMA (Blackwell FFMA2; only reachable via PTX)
DEV_INLINE void ffma2(unsigned long long& d, unsigned long long a, unsigned long long b) {
    asm("fma.rn.f32x2 %0, %1, %2, %0;" : "+l"(d) : "l"(a), "l"(b));
}

// FMA-only exp (avoids MUFU bottleneck: 268M exps would cost ~2ms on MUFU pipe)
DEV_INLINE float fast_expf(float x) {
    float t = x * 1.4426950408889634f;       // -> exp2 domain
    t = fmaxf(t, -126.0f);
    float n = floorf(t);
    float f = t - n;                          // f in [0,1)
    float r = 1.5495262e-4f;                  // Taylor of 2^f (ln2^k/k!)
    r = fmaf(r, f, 1.3333558e-3f);
    r = fmaf(r, f, 9.6181291e-3f);
    r = fmaf(r, f, 5.5504109e-2f);
    r = fmaf(r, f, 2.4022651e-1f);
    r = fmaf(r, f, 6.9314718e-1f);
    r = fmaf(r, f, 1.0f);
    float s = __int_as_float(((int)n + 127) << 23);
    return r * s;
}

// ============================================================================
// GEMM: C[M,N] = A[M,K] @ W[K,N] + bias  (128x128x16 tile, 256 thr, FFMA2)
// A duplicated in smem (broadcast operand for f32x2), B plain.
// ============================================================================
__global__ __launch_bounds__(256, 2)
void sgemm_bias(const float* __restrict__ A, const float* __restrict__ W,
                const float* __restrict__ bias, float* __restrict__ C,
                int M, int N, int K)
{
    __shared__ float As[16][256];   // k x (2*row) duplicated
    __shared__ float Bs[16][128];   // k x col
    const int tid = threadIdx.x;
    const int bx = blockIdx.x, by = blockIdx.y;
    const float* Ab = A + (size_t)by * 128 * K;
    const float* Wb = W + bx * 128;
    const int arow = tid >> 1;
    const int acol = (tid & 1) << 3;
    const int tx = tid & 15, ty = tid >> 4;

    unsigned long long acc[8][4];
#pragma unroll
    for (int i = 0; i < 8; i++)
#pragma unroll
        for (int j = 0; j < 4; j++) acc[i][j] = 0ull;

    for (int k0 = 0; k0 < K; k0 += 16) {
        float4 a0 = *(const float4*)(Ab + (size_t)arow * K + k0 + acol);
        float4 a1 = *(const float4*)(Ab + (size_t)arow * K + k0 + acol + 4);
        As[acol + 0][2*arow] = a0.x; As[acol + 0][2*arow + 1] = a0.x;
        As[acol + 1][2*arow] = a0.y; As[acol + 1][2*arow + 1] = a0.y;
        As[acol + 2][2*arow] = a0.z; As[acol + 2][2*arow + 1] = a0.z;
        As[acol + 3][2*arow] = a0.w; As[acol + 3][2*arow + 1] = a0.w;
        As[acol + 4][2*arow] = a1.x; As[acol + 4][2*arow + 1] = a1.x;
        As[acol + 5][2*arow] = a1.y; As[acol + 5][2*arow + 1] = a1.y;
        As[acol + 6][2*arow] = a1.z; As[acol + 6][2*arow + 1] = a1.z;
        As[acol + 7][2*arow] = a1.w; As[acol + 7][2*arow + 1] = a1.w;
#pragma unroll
        for (int i = 0; i < 2; i++) {
            int gid = i * 256 + tid;
            int r = gid >> 5, c = (gid & 31) << 2;
            *(float4*)&Bs[r][c] = *(const float4*)(Wb + (size_t)(k0 + r) * N + c);
        }
        __syncthreads();
#pragma unroll
        for (int kk = 0; kk < 16; kk++) {
            unsigned long long av[8] __align__(16);
            unsigned long long bv[4] __align__(16);
            *(float4*)&av[0] = *(const float4*)&As[kk][ty * 16 + 0];
            *(float4*)&av[2] = *(const float4*)&As[kk][ty * 16 + 4];
            *(float4*)&av[4] = *(const float4*)&As[kk][ty * 16 + 8];
            *(float4*)&av[6] = *(const float4*)&As[kk][ty * 16 + 12];
            *(float4*)&bv[0] = *(const float4*)&Bs[kk][tx * 4];
            *(float4*)&bv[2] = *(const float4*)&Bs[kk][64 + tx * 4];
#pragma unroll
            for (int i = 0; i < 8; i++)
#pragma unroll
                for (int j = 0; j < 4; j++) ffma2(acc[i][j], av[i], bv[j]);
        }
        __syncthreads();
    }
#pragma unroll
    for (int i = 0; i < 8; i++) {
        size_t m = (size_t)by * 128 + ty * 8 + i;
#pragma unroll
        for (int j = 0; j < 4; j++) {
            int n = bx * 128 + ((j < 2) ? (tx * 4 + 2 * j) : (64 + tx * 4 + 2 * (j - 2)));
            float2 v = *(float2*)&acc[i][j];
            C[m * N + n]     = v.x + bias[n];
            C[m * N + n + 1] = v.y + bias[n + 1];
        }
    }
}

// ============================================================================
// Suffix-sum of V per (b,h): Suf[q] = sum_{k>q} V[k]   (2-kernel scan)
// ============================================================================
__global__ __launch_bounds__(128)
void v_chunk_sum(const float* __restrict__ V, float* __restrict__ cs)
{
    int idx = blockIdx.x;            // b*512 + h*32 + c
    int c = idx & 31;
    int h = (idx >> 5) & 15;
    int b = idx >> 9;
    int d = threadIdx.x;
    size_t base = ((size_t)b * S_ + c * 64) * D_ + h * DH_ + d;
    float s = 0.f;
    for (int r = 0; r < 64; r++) s += V[base + (size_t)r * D_];
    cs[(size_t)idx * DH_ + d] = s;
}

__global__ __launch_bounds__(128)
void v_suffix(const float* __restrict__ V, const float* __restrict__ cs,
              float* __restrict__ Suf)
{
    int idx = blockIdx.x;
    int c = idx & 31;
    int h = (idx >> 5) & 15;
    int b = idx >> 9;
    int d = threadIdx.x;
    int bh = idx >> 5;               // b*16 + h
    float acc = 0.f;
    for (int c2 = c + 1; c2 < 32; c2++) acc += cs[((size_t)bh * 32 + c2) * DH_ + d];
    size_t base = ((size_t)b * S_ + c * 64) * D_ + h * DH_ + d;
    for (int r = 63; r >= 0; r--) {
        Suf[base + (size_t)r * D_] = acc;
        acc += V[base + (size_t)r * D_];
    }
}

// ============================================================================
// Flash attention with FULL-ROW softmax (mask only gates the P*V accumulate),
// epilogue adds -1e9 * suffix-sum(V) term (mask-after-softmax semantics).
// 64x64 tiles, DH=128. Smem stride 132 kills bank-column conflicts.
// ============================================================================
constexpr int SPAD = 132;
constexpr int SSROW = 65;
constexpr int FL_SMEM_FLOATS = 3 * 64 * SPAD + 64 * SSROW + 256 + 256 + 64 * 3;
constexpr int FL_SMEM_BYTES = FL_SMEM_FLOATS * 4;   // 120832

__global__ __launch_bounds__(256, 1)
void flash_attn(const float* __restrict__ Qp, const float* __restrict__ Kp,
                const float* __restrict__ Vp, const float* __restrict__ Suf,
                float* __restrict__ ctx)
{
    extern __shared__ float sm[];
    float* Qs   = sm;
    float* Ks   = Qs + 64 * SPAD;
    float* Vs   = Ks + 64 * SPAD;
    float* Ss   = Vs + 64 * SPAD;
    float* redm = Ss + 64 * SSROW;
    float* reds = redm + 256;
    float* mrow = reds + 256;
    float* lrow = mrow + 64;
    float* rsc  = lrow + 64;

    const int tid = threadIdx.x;
    const int bh = blockIdx.x;
    const int qt = blockIdx.y;
    const int b = bh >> 4, h = bh & 15;
    const size_t base_bh = (size_t)b * S_ * D_ + h * DH_;
    const int q0 = qt * 64;
    const int tx = tid & 15, ty = tid >> 4;

    if (tid < 64) { mrow[tid] = -3.0e38f; lrow[tid] = 0.f; }
#pragma unroll
    for (int i = 0; i < 8; i++) {
        int f4 = i * 256 + tid;
        int r = f4 >> 5, c4 = (f4 & 31) << 2;
        *(float4*)&Qs[r * SPAD + c4] =
            *(const float4*)(Qp + base_bh + (size_t)(q0 + r) * D_ + c4);
    }

    float acc[4][8];
#pragma unroll
    for (int i = 0; i < 4; i++)
#pragma unroll
        for (int j = 0; j < 8; j++) acc[i][j] = 0.f;

    for (int kt = 0; kt < 32; kt++) {
        __syncthreads();   // protect smem from previous iteration's readers
        const int k0 = kt * 64;
#pragma unroll
        for (int i = 0; i < 8; i++) {
            int f4 = i * 256 + tid;
            int r = f4 >> 5, c4 = (f4 & 31) << 2;
            *(float4*)&Ks[r * SPAD + c4] =
                *(const float4*)(Kp + base_bh + (size_t)(k0 + r) * D_ + c4);
            *(float4*)&Vs[r * SPAD + c4] =
                *(const float4*)(Vp + base_bh + (size_t)(k0 + r) * D_ + c4);
        }
        __syncthreads();

        // --- scores: S = Q K^T * scale (rows ty*4.., cols strided tx+16j) ---
        {
            float sc[4][4];
#pragma unroll
            for (int i = 0; i < 4; i++)
#pragma unroll
                for (int j = 0; j < 4; j++) sc[i][j] = 0.f;
#pragma unroll 2
            for (int d = 0; d < 128; d += 4) {
                float4 qv[4], kv[4];
#pragma unroll
                for (int i = 0; i < 4; i++)
                    qv[i] = *(const float4*)&Qs[(ty * 4 + i) * SPAD + d];
#pragma unroll
                for (int j = 0; j < 4; j++)
                    kv[j] = *(const float4*)&Ks[(tx + 16 * j) * SPAD + d];
#pragma unroll
                for (int i = 0; i < 4; i++)
#pragma unroll
                    for (int j = 0; j < 4; j++) {
                        sc[i][j] = fmaf(qv[i].x, kv[j].x, sc[i][j]);
                        sc[i][j] = fmaf(qv[i].y, kv[j].y, sc[i][j]);
                        sc[i][j] = fmaf(qv[i].z, kv[j].z, sc[i][j]);
                        sc[i][j] = fmaf(qv[i].w, kv[j].w, sc[i][j]);
                    }
            }
#pragma unroll
            for (int i = 0; i < 4; i++)
#pragma unroll
                for (int j = 0; j < 4; j++)
                    Ss[(ty * 4 + i) * SSROW + tx + 16 * j] =
                        sc[i][j] * 0.08838834764831845f;
        }
        __syncthreads();

        // --- row max partials ---
        {
            int row = tid & 63, part = tid >> 6;
            float mx = -3.0e38f;
#pragma unroll
            for (int c2 = 0; c2 < 16; c2++)
                mx = fmaxf(mx, Ss[row * SSROW + part * 16 + c2]);
            redm[part * 64 + row] = mx;
        }
        __syncthreads();
        if (tid < 64) {
            float mo = mrow[tid];
            float mn = fmaxf(fmaxf(redm[tid], redm[64 + tid]),
                             fmaxf(redm[128 + tid], redm[192 + tid]));
            mn = fmaxf(mn, mo);
            mrow[tid] = mn;
            rsc[tid] = fast_expf(mo - mn);
        }
        __syncthreads();

        // --- exp pass (stats over ALL cols; zero masked cols for PV only) ---
        {
            int row = tid & 63, part = tid >> 6;
            float mn = mrow[row];
            float ssum = 0.f;
            const bool diag = (kt == qt);
#pragma unroll
            for (int c2 = 0; c2 < 16; c2++) {
                int col = part * 16 + c2;
                float e = fast_expf(Ss[row * SSROW + col] - mn);
                ssum += e;
                Ss[row * SSROW + col] = (diag && col > row) ? 0.f : e;
            }
            reds[part * 64 + row] = ssum;
        }
        __syncthreads();
        if (tid < 64)
            lrow[tid] = lrow[tid] * rsc[tid]
                      + reds[tid] + reds[64 + tid] + reds[128 + tid] + reds[192 + tid];

        // --- rescale acc, then PV (skip fully-future tiles) ---
#pragma unroll
        for (int i = 0; i < 4; i++) {
            float s = rsc[ty * 4 + i];
#pragma unroll
            for (int j = 0; j < 8; j++) acc[i][j] *= s;
        }
        if (kt <= qt) {
#pragma unroll 4
            for (int kk = 0; kk < 64; kk++) {
                float4 v0 = *(const float4*)&Vs[kk * SPAD + tx * 8];
                float4 v1 = *(const float4*)&Vs[kk * SPAD + tx * 8 + 4];
#pragma unroll
                for (int i = 0; i < 4; i++) {
                    float p = Ss[(ty * 4 + i) * SSROW + kk];
                    acc[i][0] = fmaf(p, v0.x, acc[i][0]);
                    acc[i][1] = fmaf(p, v0.y, acc[i][1]);
                    acc[i][2] = fmaf(p, v0.z, acc[i][2]);
                    acc[i][3] = fmaf(p, v0.w, acc[i][3]);
                    acc[i][4] = fmaf(p, v1.x, acc[i][4]);
                    acc[i][5] = fmaf(p, v1.y, acc[i][5]);
                    acc[i][6] = fmaf(p, v1.z, acc[i][6]);
                    acc[i][7] = fmaf(p, v1.w, acc[i][7]);
                }
            }
        }
    }
    __syncthreads();

    // epilogue: ctx = acc/Z - 1e9 * suffix-sum(V)
#pragma unroll
    for (int i = 0; i < 4; i++) {
        int q = q0 + ty * 4 + i;
        float inv = 1.f / lrow[ty * 4 + i];
        size_t ob = base_bh + (size_t)q * D_ + tx * 8;
#pragma unroll
        for (int j = 0; j < 8; j++)
            ctx[ob + j] = acc[i][j] * inv - 1.0e9f * Suf[ob + j];
    }
}

// ============================================================================
extern "C" void kernel_launch(void* const* d_in, const int* in_sizes, int n_in,
                              void* d_out, int out_size)
{
    const float* q  = (const float*)d_in[0];
    const float* k  = (const float*)d_in[1];
    const float* v  = (const float*)d_in[2];
    const float* Wq = (const float*)d_in[3];
    const float* bq = (const float*)d_in[4];
    const float* Wk = (const float*)d_in[5];
    const float* bk = (const float*)d_in[6];
    const float* Wv = (const float*)d_in[7];
    const float* bvv = (const float*)d_in[8];
    const float* Wo = (const float*)d_in[9];
    const float* bo = (const float*)d_in[10];
    // d_in[11] = mask (known causal tril; semantics folded analytically)
    float* out = (float*)d_out;
    (void)in_sizes; (void)n_in; (void)out_size;

    float *gQ, *gK, *gV, *gSuf, *gctx, *gcs;
    cudaGetSymbolAddress((void**)&gQ,   g_Q);
    cudaGetSymbolAddress((void**)&gK,   g_K);
    cudaGetSymbolAddress((void**)&gV,   g_V);
    cudaGetSymbolAddress((void**)&gSuf, g_Suf);
    cudaGetSymbolAddress((void**)&gctx, g_ctx);
    cudaGetSymbolAddress((void**)&gcs,  g_csum);

    cudaFuncSetAttribute(flash_attn, cudaFuncAttributeMaxDynamicSharedMemorySize,
                         FL_SMEM_BYTES);

    dim3 gg(D_ / 128, M_ / 128);
    sgemm_bias<<<gg, 256>>>(q, Wq, bq, gQ, M_, D_, D_);
    sgemm_bias<<<gg, 256>>>(k, Wk, bk, gK, M_, D_, D_);
    sgemm_bias<<<gg, 256>>>(v, Wv, bvv, gV, M_, D_, D_);
    v_chunk_sum<<<Bb_ * H_ * 32, 128>>>(gV, gcs);
    v_suffix<<<Bb_ * H_ * 32, 128>>>(gV, gcs, gSuf);
    flash_attn<<<dim3(Bb_ * H_, 32), 256, FL_SMEM_BYTES>>>(gQ, gK, gV, gSuf, gctx);
    sgemm_bias<<<gg, 256>>>(gctx, Wo, bo, out, M_, D_, D_);
}

// round 4
// speedup vs baseline: 2.9584x; 2.9584x over previous
#include <cuda_runtime.h>
#include <cuda_bf16.h>
#include <cuda.h>
#include <cstdint>

// Problem constants
constexpr int Bb_ = 4, S_ = 2048, D_ = 2048, H_ = 16, DH_ = 128;
constexpr int M_ = Bb_ * S_;  // 8192
constexpr int Kd = 2048, Nd = 2048;

// Scratch (static __device__ — no allocations allowed)
__device__ float g_Q[M_ * D_];
__device__ float g_K[M_ * D_];
__device__ float g_V[M_ * D_];
__device__ float g_Suf[M_ * D_];
__device__ float g_ctx[M_ * D_];
__device__ float g_csum[Bb_ * H_ * 32 * DH_];
__device__ __nv_bfloat16 g_Ahi[M_ * D_];
__device__ __nv_bfloat16 g_Alo[M_ * D_];
__device__ __nv_bfloat16 g_Wthi[4][D_ * D_];
__device__ __nv_bfloat16 g_Wtlo[4][D_ * D_];

#define DEV_INLINE __device__ __forceinline__

// ======================= PTX helpers (portable, non-"a") ====================
DEV_INLINE uint32_t s2u(const void* p) {
    uint32_t a;
    asm("{ .reg .u64 t; cvta.to.shared.u64 t, %1; cvt.u32.u64 %0, t; }"
        : "=r"(a) : "l"(p));
    return a;
}
DEV_INLINE void mbar_init(uint32_t a, uint32_t c) {
    asm volatile("mbarrier.init.shared.b64 [%0], %1;" :: "r"(a), "r"(c) : "memory");
}
DEV_INLINE void mbar_expect_tx(uint32_t a, uint32_t bytes) {
    asm volatile("mbarrier.arrive.expect_tx.shared.b64 _, [%0], %1;"
                 :: "r"(a), "r"(bytes) : "memory");
}
DEV_INLINE void mbar_wait(uint32_t a, uint32_t ph) {
    asm volatile(
        "{ .reg .pred P;\n\t"
        "WL%=:\n\t"
        "mbarrier.try_wait.parity.acquire.cta.shared::cta.b64 P, [%0], %1, 0x989680;\n\t"
        "@P bra WD%=;\n\t"
        "bra WL%=;\n\t"
        "WD%=: }\n\t"
        :: "r"(a), "r"(ph) : "memory");
}
DEV_INLINE void fence_mbar_init() {
    asm volatile("fence.mbarrier_init.release.cluster;" ::: "memory");
}
DEV_INLINE void tma2d(uint32_t dst, const void* map, int x, int y, uint32_t mbar) {
    asm volatile(
        "cp.async.bulk.tensor.2d.shared::cluster.global.tile.mbarrier::complete_tx::bytes "
        "[%0], [%1, {%2, %3}], [%4];"
        :: "r"(dst), "l"(map), "r"(x), "r"(y), "r"(mbar) : "memory");
}
DEV_INLINE void ldsm4(uint32_t (&r)[4], uint32_t addr) {
    asm volatile("ldmatrix.sync.aligned.m8n8.x4.shared.b16 {%0,%1,%2,%3}, [%4];"
                 : "=r"(r[0]), "=r"(r[1]), "=r"(r[2]), "=r"(r[3]) : "r"(addr));
}
DEV_INLINE void mma16816(float (&d)[4], const uint32_t (&a)[4], uint32_t b0, uint32_t b1) {
    asm volatile(
        "mma.sync.aligned.m16n8k16.row.col.f32.bf16.bf16.f32 "
        "{%0,%1,%2,%3}, {%4,%5,%6,%7}, {%8,%9}, {%0,%1,%2,%3};"
        : "+f"(d[0]), "+f"(d[1]), "+f"(d[2]), "+f"(d[3])
        : "r"(a[0]), "r"(a[1]), "r"(a[2]), "r"(a[3]), "r"(b0), "r"(b1));
}

// FMA-only exp
DEV_INLINE float fast_expf(float x) {
    float t = x * 1.4426950408889634f;
    t = fmaxf(t, -126.0f);
    float n = floorf(t);
    float f = t - n;
    float r = 1.5495262e-4f;
    r = fmaf(r, f, 1.3333558e-3f);
    r = fmaf(r, f, 9.6181291e-3f);
    r = fmaf(r, f, 5.5504109e-2f);
    r = fmaf(r, f, 2.4022651e-1f);
    r = fmaf(r, f, 6.9314718e-1f);
    r = fmaf(r, f, 1.0f);
    float s = __int_as_float(((int)n + 127) << 23);
    return r * s;
}

// ============================================================================
// Conversion kernels: fp32 -> bf16 hi/lo split
// ============================================================================
__global__ __launch_bounds__(256)
void conv_split(const float* __restrict__ x, __nv_bfloat16* __restrict__ hi,
                __nv_bfloat16* __restrict__ lo, int n)
{
    int i = (blockIdx.x * 256 + threadIdx.x) * 4;
    if (i >= n) return;
    float4 v = *(const float4*)(x + i);
    __nv_bfloat16 h0 = __float2bfloat16(v.x);
    __nv_bfloat16 h1 = __float2bfloat16(v.y);
    __nv_bfloat16 h2 = __float2bfloat16(v.z);
    __nv_bfloat16 h3 = __float2bfloat16(v.w);
    *(__nv_bfloat162*)(hi + i)     = __halves2bfloat162(h0, h1);
    *(__nv_bfloat162*)(hi + i + 2) = __halves2bfloat162(h2, h3);
    __nv_bfloat16 l0 = __float2bfloat16(v.x - __bfloat162float(h0));
    __nv_bfloat16 l1 = __float2bfloat16(v.y - __bfloat162float(h1));
    __nv_bfloat16 l2 = __float2bfloat16(v.z - __bfloat162float(h2));
    __nv_bfloat16 l3 = __float2bfloat16(v.w - __bfloat162float(h3));
    *(__nv_bfloat162*)(lo + i)     = __halves2bfloat162(l0, l1);
    *(__nv_bfloat162*)(lo + i + 2) = __halves2bfloat162(l2, l3);
}

// W [K,N] fp32 -> Wt [N,K] bf16 hi/lo (transpose + split)
__global__ __launch_bounds__(256)
void conv_wt(const float* __restrict__ W, __nv_bfloat16* __restrict__ Thi,
             __nv_bfloat16* __restrict__ Tlo)
{
    __shared__ float t[32][33];
    int n0 = blockIdx.x * 32, k0 = blockIdx.y * 32;
    int tx = threadIdx.x & 31, ty = threadIdx.x >> 5;  // 32 x 8
    for (int r = ty; r < 32; r += 8)
        t[r][tx] = W[(size_t)(k0 + r) * Nd + n0 + tx];
    __syncthreads();
    for (int r = ty; r < 32; r += 8) {
        float x = t[tx][r];  // = W[k0+tx][n0+r]
        __nv_bfloat16 h = __float2bfloat16(x);
        Thi[(size_t)(n0 + r) * Kd + k0 + tx] = h;
        Tlo[(size_t)(n0 + r) * Kd + k0 + tx] =
            __float2bfloat16(x - __bfloat162float(h));
    }
}

// ============================================================================
// HMMA bf16x3 GEMM: C[M,N] = A @ W + bias, W given as Wt [N,K] (K-major)
// Tile 128x128, BK=64, 2-stage TMA double buffer, SW128 swizzle, 8 warps.
// ============================================================================
constexpr int GM_BM = 128, GM_BN = 128, GM_BK = 64;
constexpr int OFF_AHI = 0, OFF_ALO = 16384, OFF_BHI = 32768, OFF_BLO = 49152;
constexpr int STG_SZ = 65536;
constexpr int GM_SMEM = 1024 + 2 * STG_SZ + 64;  // padding for 1KB align + barriers

// swizzled smem offset for (row r, 16B-chunk c) within a 128-row x 128B tile
DEV_INLINE uint32_t tile_off(int r, int c) {
    return (uint32_t)(r * 128 + ((c ^ (r & 7)) << 4));
}

__global__ __launch_bounds__(256, 1)
void hgemm_bf16x3(const __grid_constant__ CUtensorMap mAhi,
                  const __grid_constant__ CUtensorMap mAlo,
                  const __grid_constant__ CUtensorMap mBhi,
                  const __grid_constant__ CUtensorMap mBlo,
                  const float* __restrict__ bias, float* __restrict__ C)
{
    extern __shared__ char smraw[];
    uint32_t smb = (s2u(smraw) + 1023u) & ~1023u;   // 1KB aligned tile base
    const uint32_t full0 = smb + 2 * STG_SZ;
    const uint32_t full1 = full0 + 8;

    const int tid = threadIdx.x;
    const int wid = tid >> 5, lane = tid & 31;
    const int m0 = blockIdx.y * GM_BM;
    const int n0 = blockIdx.x * GM_BN;
    const int warp_m = (wid & 3) * 32;
    const int warp_n = (wid >> 2) * 64;

    if (tid == 0) {
        mbar_init(full0, 1);
        mbar_init(full1, 1);
        fence_mbar_init();
    }
    __syncthreads();

    // lane-invariant fragment addressing precompute
    const int mat = lane >> 3, l7 = lane & 7;
    const int hbA = mat >> 1;                 // A: k-chunk low bit
    const int rA = ((mat & 1) << 3) + l7;     // A: row within m16
    const int hbB = mat & 1;                  // B: k-chunk low bit
    const int rB = ((mat >> 1) << 3) + l7;    // B: row within n16 pair

    float acc[2][8][4];
#pragma unroll
    for (int i = 0; i < 2; i++)
#pragma unroll
        for (int j = 0; j < 8; j++)
#pragma unroll
            for (int q = 0; q < 4; q++) acc[i][j][q] = 0.f;

    // prologue: chunk 0 -> stage 0
    if (tid == 0) {
        mbar_expect_tx(full0, 4 * 16384);
        tma2d(smb + OFF_AHI, &mAhi, 0, m0, full0);
        tma2d(smb + OFF_ALO, &mAlo, 0, m0, full0);
        tma2d(smb + OFF_BHI, &mBhi, 0, n0, full0);
        tma2d(smb + OFF_BLO, &mBlo, 0, n0, full0);
    }

    const int NCH = Kd / GM_BK;  // 32
    for (int c = 0; c < NCH; c++) {
        const int s = c & 1;
        const uint32_t sb = smb + s * STG_SZ;
        mbar_wait(s == 0 ? full0 : full1, (c >> 1) & 1);
        if (tid == 0 && c + 1 < NCH) {
            const uint32_t sb2 = smb + (s ^ 1) * STG_SZ;
            const uint32_t fb2 = (s == 0) ? full1 : full0;
            mbar_expect_tx(fb2, 4 * 16384);
            int kx = (c + 1) * GM_BK;
            tma2d(sb2 + OFF_AHI, &mAhi, kx, m0, fb2);
            tma2d(sb2 + OFF_ALO, &mAlo, kx, m0, fb2);
            tma2d(sb2 + OFF_BHI, &mBhi, kx, n0, fb2);
            tma2d(sb2 + OFF_BLO, &mBlo, kx, n0, fb2);
        }

#pragma unroll
        for (int ks = 0; ks < 4; ks++) {
            uint32_t ah[2][4], al[2][4], bh[4][4], bl[4][4];
#pragma unroll
            for (int im = 0; im < 2; im++) {
                int row = warp_m + im * 16 + rA;
                int ch = ks * 2 + hbA;
                ldsm4(ah[im], sb + OFF_AHI + tile_off(row, ch));
                ldsm4(al[im], sb + OFF_ALO + tile_off(row, ch));
            }
#pragma unroll
            for (int p = 0; p < 4; p++) {
                int row = warp_n + p * 16 + rB;
                int ch = ks * 2 + hbB;
                ldsm4(bh[p], sb + OFF_BHI + tile_off(row, ch));
                ldsm4(bl[p], sb + OFF_BLO + tile_off(row, ch));
            }
#pragma unroll
            for (int im = 0; im < 2; im++)
#pragma unroll
                for (int p = 0; p < 4; p++) {
                    mma16816(acc[im][2 * p],     ah[im], bh[p][0], bh[p][1]);
                    mma16816(acc[im][2 * p],     ah[im], bl[p][0], bl[p][1]);
                    mma16816(acc[im][2 * p],     al[im], bh[p][0], bh[p][1]);
                    mma16816(acc[im][2 * p + 1], ah[im], bh[p][2], bh[p][3]);
                    mma16816(acc[im][2 * p + 1], ah[im], bl[p][2], bl[p][3]);
                    mma16816(acc[im][2 * p + 1], al[im], bh[p][2], bh[p][3]);
                }
        }
        __syncthreads();   // stage s fully consumed before overwrite
    }

    // epilogue: fragment-layout stores + bias
    const int rowg = lane >> 2, colg = (lane & 3) * 2;
#pragma unroll
    for (int im = 0; im < 2; im++) {
#pragma unroll
        for (int jn = 0; jn < 8; jn++) {
            int n = n0 + warp_n + jn * 8 + colg;
            float2 bv = *(const float2*)(bias + n);
            size_t r0 = (size_t)(m0 + warp_m + im * 16 + rowg) * Nd + n;
            float2 v0 = {acc[im][jn][0] + bv.x, acc[im][jn][1] + bv.y};
            *(float2*)(C + r0) = v0;
            float2 v1 = {acc[im][jn][2] + bv.x, acc[im][jn][3] + bv.y};
            *(float2*)(C + r0 + 8 * Nd) = v1;
        }
    }
}

// ============================================================================
// Suffix-sum of V per (b,h)
// ============================================================================
__global__ __launch_bounds__(128)
void v_chunk_sum(const float* __restrict__ V, float* __restrict__ cs)
{
    int idx = blockIdx.x;
    int c = idx & 31;
    int h = (idx >> 5) & 15;
    int b = idx >> 9;
    int d = threadIdx.x;
    size_t base = ((size_t)b * S_ + c * 64) * D_ + h * DH_ + d;
    float s = 0.f;
    for (int r = 0; r < 64; r++) s += V[base + (size_t)r * D_];
    cs[(size_t)idx * DH_ + d] = s;
}

__global__ __launch_bounds__(128)
void v_suffix(const float* __restrict__ V, const float* __restrict__ cs,
              float* __restrict__ Suf)
{
    int idx = blockIdx.x;
    int c = idx & 31;
    int h = (idx >> 5) & 15;
    int b = idx >> 9;
    int d = threadIdx.x;
    int bh = idx >> 5;
    float acc = 0.f;
    for (int c2 = c + 1; c2 < 32; c2++) acc += cs[((size_t)bh * 32 + c2) * DH_ + d];
    size_t base = ((size_t)b * S_ + c * 64) * D_ + h * DH_ + d;
    for (int r = 63; r >= 0; r--) {
        Suf[base + (size_t)r * D_] = acc;
        acc += V[base + (size_t)r * D_];
    }
}

// ============================================================================
// Flash attention (full-row softmax, mask gates PV; -1e9*suffix(V) epilogue)
// ============================================================================
constexpr int SPAD = 132;
constexpr int SSROW = 65;
constexpr int FL_SMEM_FLOATS = 3 * 64 * SPAD + 64 * SSROW + 256 + 256 + 64 * 3;
constexpr int FL_SMEM_BYTES = FL_SMEM_FLOATS * 4;

__global__ __launch_bounds__(256, 1)
void flash_attn(const float* __restrict__ Qp, const float* __restrict__ Kp,
                const float* __restrict__ Vp, const float* __restrict__ Suf,
                float* __restrict__ ctx)
{
    extern __shared__ float sm[];
    float* Qs   = sm;
    float* Ks   = Qs + 64 * SPAD;
    float* Vs   = Ks + 64 * SPAD;
    float* Ss   = Vs + 64 * SPAD;
    float* redm = Ss + 64 * SSROW;
    float* reds = redm + 256;
    float* mrow = reds + 256;
    float* lrow = mrow + 64;
    float* rsc  = lrow + 64;

    const int tid = threadIdx.x;
    const int bh = blockIdx.x;
    const int qt = blockIdx.y;
    const int b = bh >> 4, h = bh & 15;
    const size_t base_bh = (size_t)b * S_ * D_ + h * DH_;
    const int q0 = qt * 64;
    const int tx = tid & 15, ty = tid >> 4;

    if (tid < 64) { mrow[tid] = -3.0e38f; lrow[tid] = 0.f; }
#pragma unroll
    for (int i = 0; i < 8; i++) {
        int f4 = i * 256 + tid;
        int r = f4 >> 5, c4 = (f4 & 31) << 2;
        *(float4*)&Qs[r * SPAD + c4] =
            *(const float4*)(Qp + base_bh + (size_t)(q0 + r) * D_ + c4);
    }

    float acc[4][8];
#pragma unroll
    for (int i = 0; i < 4; i++)
#pragma unroll
        for (int j = 0; j < 8; j++) acc[i][j] = 0.f;

    for (int kt = 0; kt < 32; kt++) {
        __syncthreads();
        const int k0 = kt * 64;
#pragma unroll
        for (int i = 0; i < 8; i++) {
            int f4 = i * 256 + tid;
            int r = f4 >> 5, c4 = (f4 & 31) << 2;
            *(float4*)&Ks[r * SPAD + c4] =
                *(const float4*)(Kp + base_bh + (size_t)(k0 + r) * D_ + c4);
            *(float4*)&Vs[r * SPAD + c4] =
                *(const float4*)(Vp + base_bh + (size_t)(k0 + r) * D_ + c4);
        }
        __syncthreads();

        {
            float sc[4][4];
#pragma unroll
            for (int i = 0; i < 4; i++)
#pragma unroll
                for (int j = 0; j < 4; j++) sc[i][j] = 0.f;
#pragma unroll 2
            for (int d = 0; d < 128; d += 4) {
                float4 qv[4], kv[4];
#pragma unroll
                for (int i = 0; i < 4; i++)
                    qv[i] = *(const float4*)&Qs[(ty * 4 + i) * SPAD + d];
#pragma unroll
                for (int j = 0; j < 4; j++)
                    kv[j] = *(const float4*)&Ks[(tx + 16 * j) * SPAD + d];
#pragma unroll
                for (int i = 0; i < 4; i++)
#pragma unroll
                    for (int j = 0; j < 4; j++) {
                        sc[i][j] = fmaf(qv[i].x, kv[j].x, sc[i][j]);
                        sc[i][j] = fmaf(qv[i].y, kv[j].y, sc[i][j]);
                        sc[i][j] = fmaf(qv[i].z, kv[j].z, sc[i][j]);
                        sc[i][j] = fmaf(qv[i].w, kv[j].w, sc[i][j]);
                    }
            }
#pragma unroll
            for (int i = 0; i < 4; i++)
#pragma unroll
                for (int j = 0; j < 4; j++)
                    Ss[(ty * 4 + i) * SSROW + tx + 16 * j] =
                        sc[i][j] * 0.08838834764831845f;
        }
        __syncthreads();

        {
            int row = tid & 63, part = tid >> 6;
            float mx = -3.0e38f;
#pragma unroll
            for (int c2 = 0; c2 < 16; c2++)
                mx = fmaxf(mx, Ss[row * SSROW + part * 16 + c2]);
            redm[part * 64 + row] = mx;
        }
        __syncthreads();
        if (tid < 64) {
            float mo = mrow[tid];
            float mn = fmaxf(fmaxf(redm[tid], redm[64 + tid]),
                             fmaxf(redm[128 + tid], redm[192 + tid]));
            mn = fmaxf(mn, mo);
            mrow[tid] = mn;
            rsc[tid] = fast_expf(mo - mn);
        }
        __syncthreads();

        {
            int row = tid & 63, part = tid >> 6;
            float mn = mrow[row];
            float ssum = 0.f;
            const bool diag = (kt == qt);
#pragma unroll
            for (int c2 = 0; c2 < 16; c2++) {
                int col = part * 16 + c2;
                float e = fast_expf(Ss[row * SSROW + col] - mn);
                ssum += e;
                Ss[row * SSROW + col] = (diag && col > row) ? 0.f : e;
            }
            reds[part * 64 + row] = ssum;
        }
        __syncthreads();
        if (tid < 64)
            lrow[tid] = lrow[tid] * rsc[tid]
                      + reds[tid] + reds[64 + tid] + reds[128 + tid] + reds[192 + tid];

#pragma unroll
        for (int i = 0; i < 4; i++) {
            float s = rsc[ty * 4 + i];
#pragma unroll
            for (int j = 0; j < 8; j++) acc[i][j] *= s;
        }
        if (kt <= qt) {
#pragma unroll 4
            for (int kk = 0; kk < 64; kk++) {
                float4 v0 = *(const float4*)&Vs[kk * SPAD + tx * 8];
                float4 v1 = *(const float4*)&Vs[kk * SPAD + tx * 8 + 4];
#pragma unroll
                for (int i = 0; i < 4; i++) {
                    float p = Ss[(ty * 4 + i) * SSROW + kk];
                    acc[i][0] = fmaf(p, v0.x, acc[i][0]);
                    acc[i][1] = fmaf(p, v0.y, acc[i][1]);
                    acc[i][2] = fmaf(p, v0.z, acc[i][2]);
                    acc[i][3] = fmaf(p, v0.w, acc[i][3]);
                    acc[i][4] = fmaf(p, v1.x, acc[i][4]);
                    acc[i][5] = fmaf(p, v1.y, acc[i][5]);
                    acc[i][6] = fmaf(p, v1.z, acc[i][6]);
                    acc[i][7] = fmaf(p, v1.w, acc[i][7]);
                }
            }
        }
    }
    __syncthreads();

#pragma unroll
    for (int i = 0; i < 4; i++) {
        int q = q0 + ty * 4 + i;
        float inv = 1.f / lrow[ty * 4 + i];
        size_t ob = base_bh + (size_t)q * D_ + tx * 8;
#pragma unroll
        for (int j = 0; j < 8; j++)
            ctx[ob + j] = acc[i][j] * inv - 1.0e9f * Suf[ob + j];
    }
}

// ============================================================================
typedef CUresult (*PFN_encodeTiled)(
    CUtensorMap*, CUtensorMapDataType, cuuint32_t, void*,
    const cuuint64_t*, const cuuint64_t*, const cuuint32_t*, const cuuint32_t*,
    CUtensorMapInterleave, CUtensorMapSwizzle, CUtensorMapL2promotion,
    CUtensorMapFloatOOBfill);

static void make_map_bf16(PFN_encodeTiled enc, CUtensorMap* m, void* ptr,
                          unsigned long long rows)
{
    cuuint64_t dims[2] = {(cuuint64_t)Kd, (cuuint64_t)rows};
    cuuint64_t strides[1] = {(cuuint64_t)Kd * 2};
    cuuint32_t box[2] = {64, 128};
    cuuint32_t es[2] = {1, 1};
    enc(m, CU_TENSOR_MAP_DATA_TYPE_BFLOAT16, 2, ptr, dims, strides, box, es,
        CU_TENSOR_MAP_INTERLEAVE_NONE, CU_TENSOR_MAP_SWIZZLE_128B,
        CU_TENSOR_MAP_L2_PROMOTION_L2_128B, CU_TENSOR_MAP_FLOAT_OOB_FILL_NONE);
}

extern "C" void kernel_launch(void* const* d_in, const int* in_sizes, int n_in,
                              void* d_out, int out_size)
{
    const float* q  = (const float*)d_in[0];
    const float* k  = (const float*)d_in[1];
    const float* v  = (const float*)d_in[2];
    const float* Wq = (const float*)d_in[3];
    const float* bq = (const float*)d_in[4];
    const float* Wk = (const float*)d_in[5];
    const float* bk = (const float*)d_in[6];
    const float* Wv = (const float*)d_in[7];
    const float* bvv = (const float*)d_in[8];
    const float* Wo = (const float*)d_in[9];
    const float* bo = (const float*)d_in[10];
    float* out = (float*)d_out;
    (void)in_sizes; (void)n_in; (void)out_size;

    float *gQ, *gK, *gV, *gSuf, *gctx, *gcs;
    cudaGetSymbolAddress((void**)&gQ,   g_Q);
    cudaGetSymbolAddress((void**)&gK,   g_K);
    cudaGetSymbolAddress((void**)&gV,   g_V);
    cudaGetSymbolAddress((void**)&gSuf, g_Suf);
    cudaGetSymbolAddress((void**)&gctx, g_ctx);
    cudaGetSymbolAddress((void**)&gcs,  g_csum);
    __nv_bfloat16 *gAhi, *gAlo, *gWthi, *gWtlo;
    cudaGetSymbolAddress((void**)&gAhi, g_Ahi);
    cudaGetSymbolAddress((void**)&gAlo, g_Alo);
    cudaGetSymbolAddress((void**)&gWthi, g_Wthi);
    cudaGetSymbolAddress((void**)&gWtlo, g_Wtlo);

    // tensormap encoder via cudart (no -lcuda needed)
    void* pfn = nullptr;
    cudaDriverEntryPointQueryResult qr;
    cudaGetDriverEntryPointByVersion("cuTensorMapEncodeTiled", &pfn, 12000,
                                     cudaEnableDefault, &qr);
    PFN_encodeTiled enc = (PFN_encodeTiled)pfn;

    const int WN = D_ * D_;
    CUtensorMap mAhi, mAlo;
    CUtensorMap mWhi[4], mWlo[4];
    make_map_bf16(enc, &mAhi, gAhi, M_);
    make_map_bf16(enc, &mAlo, gAlo, M_);
    for (int i = 0; i < 4; i++) {
        make_map_bf16(enc, &mWhi[i], gWthi + (size_t)i * WN, Nd);
        make_map_bf16(enc, &mWlo[i], gWtlo + (size_t)i * WN, Nd);
    }

    cudaFuncSetAttribute(flash_attn, cudaFuncAttributeMaxDynamicSharedMemorySize,
                         FL_SMEM_BYTES);
    cudaFuncSetAttribute(hgemm_bf16x3, cudaFuncAttributeMaxDynamicSharedMemorySize,
                         GM_SMEM);

    dim3 wg(64, 64);
    conv_wt<<<wg, 256>>>(Wq, gWthi + 0 * (size_t)WN, gWtlo + 0 * (size_t)WN);
    conv_wt<<<wg, 256>>>(Wk, gWthi + 1 * (size_t)WN, gWtlo + 1 * (size_t)WN);
    conv_wt<<<wg, 256>>>(Wv, gWthi + 2 * (size_t)WN, gWtlo + 2 * (size_t)WN);
    conv_wt<<<wg, 256>>>(Wo, gWthi + 3 * (size_t)WN, gWtlo + 3 * (size_t)WN);

    dim3 gg(Nd / GM_BN, M_ / GM_BM);  // (16, 64)
    const int NCV = M_ * D_ / 4 / 256;

    conv_split<<<NCV, 256>>>(q, gAhi, gAlo, M_ * D_);
    hgemm_bf16x3<<<gg, 256, GM_SMEM>>>(mAhi, mAlo, mWhi[0], mWlo[0], bq, gQ);
    conv_split<<<NCV, 256>>>(k, gAhi, gAlo, M_ * D_);
    hgemm_bf16x3<<<gg, 256, GM_SMEM>>>(mAhi, mAlo, mWhi[1], mWlo[1], bk, gK);
    conv_split<<<NCV, 256>>>(v, gAhi, gAlo, M_ * D_);
    hgemm_bf16x3<<<gg, 256, GM_SMEM>>>(mAhi, mAlo, mWhi[2], mWlo[2], bvv, gV);

    v_chunk_sum<<<Bb_ * H_ * 32, 128>>>(gV, gcs);
    v_suffix<<<Bb_ * H_ * 32, 128>>>(gV, gcs, gSuf);
    flash_attn<<<dim3(Bb_ * H_, 32), 256, FL_SMEM_BYTES>>>(gQ, gK, gV, gSuf, gctx);

    conv_split<<<NCV, 256>>>(gctx, gAhi, gAlo, M_ * D_);
    hgemm_bf16x3<<<gg, 256, GM_SMEM>>>(mAhi, mAlo, mWhi[3], mWlo[3], bo, out);
}

// round 5
// speedup vs baseline: 5.5360x; 1.8713x over previous
#include <cuda_runtime.h>
#include <cuda_bf16.h>
#include <cuda.h>
#include <cstdint>

// Problem constants
constexpr int Bb_ = 4, S_ = 2048, D_ = 2048, H_ = 16, DH_ = 128;
constexpr int M_ = Bb_ * S_;  // 8192
constexpr int Kd = 2048, Nd = 2048;

// Scratch (static __device__ — no allocations allowed)
__device__ float g_Q[M_ * D_];
__device__ float g_K[M_ * D_];
__device__ float g_V[M_ * D_];
__device__ float g_Suf[M_ * D_];
__device__ float g_ctx[M_ * D_];
__device__ float g_csum[Bb_ * H_ * 32 * DH_];
__device__ __nv_bfloat16 g_Ahi[M_ * D_];
__device__ __nv_bfloat16 g_Alo[M_ * D_];
__device__ __nv_bfloat16 g_Wthi[4][D_ * D_];
__device__ __nv_bfloat16 g_Wtlo[4][D_ * D_];

#define DEV_INLINE __device__ __forceinline__

// ======================= PTX helpers (portable, non-"a") ====================
DEV_INLINE uint32_t s2u(const void* p) {
    uint32_t a;
    asm("{ .reg .u64 t; cvta.to.shared.u64 t, %1; cvt.u32.u64 %0, t; }"
        : "=r"(a) : "l"(p));
    return a;
}
DEV_INLINE void mbar_init(uint32_t a, uint32_t c) {
    asm volatile("mbarrier.init.shared.b64 [%0], %1;" :: "r"(a), "r"(c) : "memory");
}
DEV_INLINE void mbar_expect_tx(uint32_t a, uint32_t bytes) {
    asm volatile("mbarrier.arrive.expect_tx.shared.b64 _, [%0], %1;"
                 :: "r"(a), "r"(bytes) : "memory");
}
DEV_INLINE void mbar_wait(uint32_t a, uint32_t ph) {
    asm volatile(
        "{ .reg .pred P;\n\t"
        "WL%=:\n\t"
        "mbarrier.try_wait.parity.acquire.cta.shared::cta.b64 P, [%0], %1, 0x989680;\n\t"
        "@P bra WD%=;\n\t"
        "bra WL%=;\n\t"
        "WD%=: }\n\t"
        :: "r"(a), "r"(ph) : "memory");
}
DEV_INLINE void fence_mbar_init() {
    asm volatile("fence.mbarrier_init.release.cluster;" ::: "memory");
}
DEV_INLINE void tma2d(uint32_t dst, const void* map, int x, int y, uint32_t mbar) {
    asm volatile(
        "cp.async.bulk.tensor.2d.shared::cluster.global.tile.mbarrier::complete_tx::bytes "
        "[%0], [%1, {%2, %3}], [%4];"
        :: "r"(dst), "l"(map), "r"(x), "r"(y), "r"(mbar) : "memory");
}
DEV_INLINE void ldsm4(uint32_t (&r)[4], uint32_t addr) {
    asm volatile("ldmatrix.sync.aligned.m8n8.x4.shared.b16 {%0,%1,%2,%3}, [%4];"
                 : "=r"(r[0]), "=r"(r[1]), "=r"(r[2]), "=r"(r[3]) : "r"(addr));
}
DEV_INLINE void mma16816(float (&d)[4], const uint32_t (&a)[4], uint32_t b0, uint32_t b1) {
    asm volatile(
        "mma.sync.aligned.m16n8k16.row.col.f32.bf16.bf16.f32 "
        "{%0,%1,%2,%3}, {%4,%5,%6,%7}, {%8,%9}, {%0,%1,%2,%3};"
        : "+f"(d[0]), "+f"(d[1]), "+f"(d[2]), "+f"(d[3])
        : "r"(a[0]), "r"(a[1]), "r"(a[2]), "r"(a[3]), "r"(b0), "r"(b1));
}

// FMA-only exp
DEV_INLINE float fast_expf(float x) {
    float t = x * 1.4426950408889634f;
    t = fmaxf(t, -126.0f);
    float n = floorf(t);
    float f = t - n;
    float r = 1.5495262e-4f;
    r = fmaf(r, f, 1.3333558e-3f);
    r = fmaf(r, f, 9.6181291e-3f);
    r = fmaf(r, f, 5.5504109e-2f);
    r = fmaf(r, f, 2.4022651e-1f);
    r = fmaf(r, f, 6.9314718e-1f);
    r = fmaf(r, f, 1.0f);
    float s = __int_as_float(((int)n + 127) << 23);
    return r * s;
}
DEV_INLINE uint32_t pack_bf2(float a, float b) {
    __nv_bfloat162 p = __halves2bfloat162(__float2bfloat16(a), __float2bfloat16(b));
    return *(uint32_t*)&p;
}

// ============================================================================
// Conversion kernels: fp32 -> bf16 hi/lo split
// ============================================================================
__global__ __launch_bounds__(256)
void conv_split(const float* __restrict__ x, __nv_bfloat16* __restrict__ hi,
                __nv_bfloat16* __restrict__ lo, int n)
{
    int i = (blockIdx.x * 256 + threadIdx.x) * 4;
    if (i >= n) return;
    float4 v = *(const float4*)(x + i);
    __nv_bfloat16 h0 = __float2bfloat16(v.x);
    __nv_bfloat16 h1 = __float2bfloat16(v.y);
    __nv_bfloat16 h2 = __float2bfloat16(v.z);
    __nv_bfloat16 h3 = __float2bfloat16(v.w);
    *(__nv_bfloat162*)(hi + i)     = __halves2bfloat162(h0, h1);
    *(__nv_bfloat162*)(hi + i + 2) = __halves2bfloat162(h2, h3);
    __nv_bfloat16 l0 = __float2bfloat16(v.x - __bfloat162float(h0));
    __nv_bfloat16 l1 = __float2bfloat16(v.y - __bfloat162float(h1));
    __nv_bfloat16 l2 = __float2bfloat16(v.z - __bfloat162float(h2));
    __nv_bfloat16 l3 = __float2bfloat16(v.w - __bfloat162float(h3));
    *(__nv_bfloat162*)(lo + i)     = __halves2bfloat162(l0, l1);
    *(__nv_bfloat162*)(lo + i + 2) = __halves2bfloat162(l2, l3);
}

// W [K,N] fp32 -> Wt [N,K] bf16 hi/lo (transpose + split)
__global__ __launch_bounds__(256)
void conv_wt(const float* __restrict__ W, __nv_bfloat16* __restrict__ Thi,
             __nv_bfloat16* __restrict__ Tlo)
{
    __shared__ float t[32][33];
    int n0 = blockIdx.x * 32, k0 = blockIdx.y * 32;
    int tx = threadIdx.x & 31, ty = threadIdx.x >> 5;  // 32 x 8
    for (int r = ty; r < 32; r += 8)
        t[r][tx] = W[(size_t)(k0 + r) * Nd + n0 + tx];
    __syncthreads();
    for (int r = ty; r < 32; r += 8) {
        float x = t[tx][r];  // = W[k0+tx][n0+r]
        __nv_bfloat16 h = __float2bfloat16(x);
        Thi[(size_t)(n0 + r) * Kd + k0 + tx] = h;
        Tlo[(size_t)(n0 + r) * Kd + k0 + tx] =
            __float2bfloat16(x - __bfloat162float(h));
    }
}

// ============================================================================
// HMMA bf16x3 GEMM (unchanged from round 4 — passing)
// ============================================================================
constexpr int GM_BM = 128, GM_BN = 128, GM_BK = 64;
constexpr int OFF_AHI = 0, OFF_ALO = 16384, OFF_BHI = 32768, OFF_BLO = 49152;
constexpr int STG_SZ = 65536;
constexpr int GM_SMEM = 1024 + 2 * STG_SZ + 64;

DEV_INLINE uint32_t tile_off(int r, int c) {
    return (uint32_t)(r * 128 + ((c ^ (r & 7)) << 4));
}

__global__ __launch_bounds__(256, 1)
void hgemm_bf16x3(const __grid_constant__ CUtensorMap mAhi,
                  const __grid_constant__ CUtensorMap mAlo,
                  const __grid_constant__ CUtensorMap mBhi,
                  const __grid_constant__ CUtensorMap mBlo,
                  const float* __restrict__ bias, float* __restrict__ C)
{
    extern __shared__ char smraw[];
    uint32_t smb = (s2u(smraw) + 1023u) & ~1023u;
    const uint32_t full0 = smb + 2 * STG_SZ;
    const uint32_t full1 = full0 + 8;

    const int tid = threadIdx.x;
    const int wid = tid >> 5, lane = tid & 31;
    const int m0 = blockIdx.y * GM_BM;
    const int n0 = blockIdx.x * GM_BN;
    const int warp_m = (wid & 3) * 32;
    const int warp_n = (wid >> 2) * 64;

    if (tid == 0) {
        mbar_init(full0, 1);
        mbar_init(full1, 1);
        fence_mbar_init();
    }
    __syncthreads();

    const int mat = lane >> 3, l7 = lane & 7;
    const int hbA = mat >> 1;
    const int rA = ((mat & 1) << 3) + l7;
    const int hbB = mat & 1;
    const int rB = ((mat >> 1) << 3) + l7;

    float acc[2][8][4];
#pragma unroll
    for (int i = 0; i < 2; i++)
#pragma unroll
        for (int j = 0; j < 8; j++)
#pragma unroll
            for (int q = 0; q < 4; q++) acc[i][j][q] = 0.f;

    if (tid == 0) {
        mbar_expect_tx(full0, 4 * 16384);
        tma2d(smb + OFF_AHI, &mAhi, 0, m0, full0);
        tma2d(smb + OFF_ALO, &mAlo, 0, m0, full0);
        tma2d(smb + OFF_BHI, &mBhi, 0, n0, full0);
        tma2d(smb + OFF_BLO, &mBlo, 0, n0, full0);
    }

    const int NCH = Kd / GM_BK;
    for (int c = 0; c < NCH; c++) {
        const int s = c & 1;
        const uint32_t sb = smb + s * STG_SZ;
        mbar_wait(s == 0 ? full0 : full1, (c >> 1) & 1);
        if (tid == 0 && c + 1 < NCH) {
            const uint32_t sb2 = smb + (s ^ 1) * STG_SZ;
            const uint32_t fb2 = (s == 0) ? full1 : full0;
            mbar_expect_tx(fb2, 4 * 16384);
            int kx = (c + 1) * GM_BK;
            tma2d(sb2 + OFF_AHI, &mAhi, kx, m0, fb2);
            tma2d(sb2 + OFF_ALO, &mAlo, kx, m0, fb2);
            tma2d(sb2 + OFF_BHI, &mBhi, kx, n0, fb2);
            tma2d(sb2 + OFF_BLO, &mBlo, kx, n0, fb2);
        }

#pragma unroll
        for (int ks = 0; ks < 4; ks++) {
            uint32_t ah[2][4], al[2][4], bh[4][4], bl[4][4];
#pragma unroll
            for (int im = 0; im < 2; im++) {
                int row = warp_m + im * 16 + rA;
                int ch = ks * 2 + hbA;
                ldsm4(ah[im], sb + OFF_AHI + tile_off(row, ch));
                ldsm4(al[im], sb + OFF_ALO + tile_off(row, ch));
            }
#pragma unroll
            for (int p = 0; p < 4; p++) {
                int row = warp_n + p * 16 + rB;
                int ch = ks * 2 + hbB;
                ldsm4(bh[p], sb + OFF_BHI + tile_off(row, ch));
                ldsm4(bl[p], sb + OFF_BLO + tile_off(row, ch));
            }
#pragma unroll
            for (int im = 0; im < 2; im++)
#pragma unroll
                for (int p = 0; p < 4; p++) {
                    mma16816(acc[im][2 * p],     ah[im], bh[p][0], bh[p][1]);
                    mma16816(acc[im][2 * p],     ah[im], bl[p][0], bl[p][1]);
                    mma16816(acc[im][2 * p],     al[im], bh[p][0], bh[p][1]);
                    mma16816(acc[im][2 * p + 1], ah[im], bh[p][2], bh[p][3]);
                    mma16816(acc[im][2 * p + 1], ah[im], bl[p][2], bl[p][3]);
                    mma16816(acc[im][2 * p + 1], al[im], bh[p][2], bh[p][3]);
                }
        }
        __syncthreads();
    }

    const int rowg = lane >> 2, colg = (lane & 3) * 2;
#pragma unroll
    for (int im = 0; im < 2; im++) {
#pragma unroll
        for (int jn = 0; jn < 8; jn++) {
            int n = n0 + warp_n + jn * 8 + colg;
            float2 bv = *(const float2*)(bias + n);
            size_t r0 = (size_t)(m0 + warp_m + im * 16 + rowg) * Nd + n;
            float2 v0 = {acc[im][jn][0] + bv.x, acc[im][jn][1] + bv.y};
            *(float2*)(C + r0) = v0;
            float2 v1 = {acc[im][jn][2] + bv.x, acc[im][jn][3] + bv.y};
            *(float2*)(C + r0 + 8 * Nd) = v1;
        }
    }
}

// ============================================================================
// Suffix-sum of V per (b,h)
// ============================================================================
__global__ __launch_bounds__(128)
void v_chunk_sum(const float* __restrict__ V, float* __restrict__ cs)
{
    int idx = blockIdx.x;
    int c = idx & 31;
    int h = (idx >> 5) & 15;
    int b = idx >> 9;
    int d = threadIdx.x;
    size_t base = ((size_t)b * S_ + c * 64) * D_ + h * DH_ + d;
    float s = 0.f;
    for (int r = 0; r < 64; r++) s += V[base + (size_t)r * D_];
    cs[(size_t)idx * DH_ + d] = s;
}

__global__ __launch_bounds__(128)
void v_suffix(const float* __restrict__ V, const float* __restrict__ cs,
              float* __restrict__ Suf)
{
    int idx = blockIdx.x;
    int c = idx & 31;
    int h = (idx >> 5) & 15;
    int b = idx >> 9;
    int d = threadIdx.x;
    int bh = idx >> 5;
    float acc = 0.f;
    for (int c2 = c + 1; c2 < 32; c2++) acc += cs[((size_t)bh * 32 + c2) * DH_ + d];
    size_t base = ((size_t)b * S_ + c * 64) * D_ + h * DH_ + d;
    for (int r = 63; r >= 0; r--) {
        Suf[base + (size_t)r * D_] = acc;
        acc += V[base + (size_t)r * D_];
    }
}

// ============================================================================
// Flash attention v2: HMMA bf16x3 for QK^T and P·V.
// 128 q-rows x 128 k-cols tiles, 8 warps (m16 each). Full-row softmax stats;
// mask gates PV only; -1e9*suffix(V) epilogue.
// ============================================================================
constexpr int FT_SMEM = 6 * 32768;  // Qhi Qlo Khi Klo VThi VTlo = 192 KB
constexpr int FQHI = 0, FQLO = 32768, FKHI = 65536, FKLO = 98304,
              FVHI = 131072, FVLO = 163840;

// swizzled byte offset in a 128-row x 256B tile (16 chunks of 16B per row)
DEV_INLINE uint32_t tile256(int r, int c) {
    return (uint32_t)(r * 256 + ((((c ^ r) & 7) | (c & 8)) << 4));
}

__global__ __launch_bounds__(256, 1)
void flash_mma(const float* __restrict__ Qp, const float* __restrict__ Kp,
               const float* __restrict__ Vp, const float* __restrict__ Suf,
               float* __restrict__ ctx)
{
    extern __shared__ char fsm[];
    const uint32_t smb = s2u(fsm);
    const int tid = threadIdx.x, wid = tid >> 5, lane = tid & 31;
    const int bh = blockIdx.x, qt = blockIdx.y;
    const int b = bh >> 4, h = bh & 15;
    const size_t base = (size_t)b * S_ * D_ + h * DH_;
    const int q0 = qt * 128;

    const int mat = lane >> 3, l7 = lane & 7;
    const int hbA = mat >> 1, rA = ((mat & 1) << 3) + l7;
    const int hbB = mat & 1, rB = ((mat >> 1) << 3) + l7;
    const int rowg = lane >> 2, colq = (lane & 3) * 2;
    const int warp_m = wid * 16;

    // ---- load & convert Q tile (once) ----
#pragma unroll
    for (int i = 0; i < 16; i++) {
        int idx = i * 256 + tid;
        int r = idx >> 5, c4 = (idx & 31) * 4;
        float4 v = *(const float4*)(Qp + base + (size_t)(q0 + r) * D_ + c4);
        uint32_t off = tile256(r, c4 >> 3) + (c4 & 4) * 2;
        uint32_t h01 = pack_bf2(v.x, v.y), h23 = pack_bf2(v.z, v.w);
        *(uint2*)(fsm + FQHI + off) = make_uint2(h01, h23);
        float hx = __bfloat162float(__float2bfloat16(v.x));
        float hy = __bfloat162float(__float2bfloat16(v.y));
        float hz = __bfloat162float(__float2bfloat16(v.z));
        float hw = __bfloat162float(__float2bfloat16(v.w));
        *(uint2*)(fsm + FQLO + off) =
            make_uint2(pack_bf2(v.x - hx, v.y - hy), pack_bf2(v.z - hz, v.w - hw));
    }

    float O[16][4];
#pragma unroll
    for (int j = 0; j < 16; j++)
#pragma unroll
        for (int q = 0; q < 4; q++) O[j][q] = 0.f;
    float m0 = -3.0e38f, m1 = -3.0e38f, l0 = 0.f, l1 = 0.f;

    for (int kt = 0; kt < 16; kt++) {
        const int k0 = kt * 128;
        __syncthreads();  // previous tile fully consumed
        // ---- load & convert K tile ----
#pragma unroll
        for (int i = 0; i < 16; i++) {
            int idx = i * 256 + tid;
            int r = idx >> 5, c4 = (idx & 31) * 4;
            float4 v = *(const float4*)(Kp + base + (size_t)(k0 + r) * D_ + c4);
            uint32_t off = tile256(r, c4 >> 3) + (c4 & 4) * 2;
            *(uint2*)(fsm + FKHI + off) =
                make_uint2(pack_bf2(v.x, v.y), pack_bf2(v.z, v.w));
            float hx = __bfloat162float(__float2bfloat16(v.x));
            float hy = __bfloat162float(__float2bfloat16(v.y));
            float hz = __bfloat162float(__float2bfloat16(v.z));
            float hw = __bfloat162float(__float2bfloat16(v.w));
            *(uint2*)(fsm + FKLO + off) =
                make_uint2(pack_bf2(v.x - hx, v.y - hy), pack_bf2(v.z - hz, v.w - hw));
        }
        // ---- load & convert V tile transposed: VT[dh][k] ----
        {
            int g = tid >> 5;
#pragma unroll
            for (int i = 0; i < 4; i++)
#pragma unroll
                for (int j = 0; j < 2; j++) {
                    int d = i * 32 + lane;
                    int kg = g * 2 + j;
                    float vv[8];
#pragma unroll
                    for (int kk = 0; kk < 8; kk++)
                        vv[kk] = Vp[base + (size_t)(k0 + kg * 8 + kk) * D_ + d];
                    uint32_t hi[4], lo[4];
#pragma unroll
                    for (int p = 0; p < 4; p++) {
                        float a = vv[2 * p], c = vv[2 * p + 1];
                        hi[p] = pack_bf2(a, c);
                        float ha = __bfloat162float(__float2bfloat16(a));
                        float hc = __bfloat162float(__float2bfloat16(c));
                        lo[p] = pack_bf2(a - ha, c - hc);
                    }
                    uint32_t off = tile256(d, kg);
                    *(uint4*)(fsm + FVHI + off) = make_uint4(hi[0], hi[1], hi[2], hi[3]);
                    *(uint4*)(fsm + FVLO + off) = make_uint4(lo[0], lo[1], lo[2], lo[3]);
                }
        }
        __syncthreads();

        // ---- S = Q K^T (bf16x3) ----
        float acc[16][4];
#pragma unroll
        for (int j = 0; j < 16; j++)
#pragma unroll
            for (int q = 0; q < 4; q++) acc[j][q] = 0.f;
#pragma unroll
        for (int ks = 0; ks < 8; ks++) {
            uint32_t ah[4], al[4];
            int arow = warp_m + rA, ach = ks * 2 + hbA;
            ldsm4(ah, smb + FQHI + tile256(arow, ach));
            ldsm4(al, smb + FQLO + tile256(arow, ach));
#pragma unroll
            for (int p = 0; p < 8; p++) {
                uint32_t bhf[4], blf[4];
                int brow = p * 16 + rB, bch = ks * 2 + hbB;
                ldsm4(bhf, smb + FKHI + tile256(brow, bch));
                ldsm4(blf, smb + FKLO + tile256(brow, bch));
                mma16816(acc[2 * p],     ah, bhf[0], bhf[1]);
                mma16816(acc[2 * p],     al, bhf[0], bhf[1]);
                mma16816(acc[2 * p],     ah, blf[0], blf[1]);
                mma16816(acc[2 * p + 1], ah, bhf[2], bhf[3]);
                mma16816(acc[2 * p + 1], al, bhf[2], bhf[3]);
                mma16816(acc[2 * p + 1], ah, blf[2], blf[3]);
            }
        }
        // scale
#pragma unroll
        for (int j = 0; j < 16; j++)
#pragma unroll
            for (int q = 0; q < 4; q++) acc[j][q] *= 0.08838834764831845f;

        // ---- online softmax (full-row stats) ----
        float mx0 = -3.0e38f, mx1 = -3.0e38f;
#pragma unroll
        for (int j = 0; j < 16; j++) {
            mx0 = fmaxf(mx0, fmaxf(acc[j][0], acc[j][1]));
            mx1 = fmaxf(mx1, fmaxf(acc[j][2], acc[j][3]));
        }
        mx0 = fmaxf(mx0, __shfl_xor_sync(0xFFFFFFFF, mx0, 1));
        mx0 = fmaxf(mx0, __shfl_xor_sync(0xFFFFFFFF, mx0, 2));
        mx1 = fmaxf(mx1, __shfl_xor_sync(0xFFFFFFFF, mx1, 1));
        mx1 = fmaxf(mx1, __shfl_xor_sync(0xFFFFFFFF, mx1, 2));
        float nm0 = fmaxf(m0, mx0), nm1 = fmaxf(m1, mx1);
        float r0 = fast_expf(m0 - nm0), r1 = fast_expf(m1 - nm1);
        m0 = nm0; m1 = nm1;

        const bool diag = (kt == qt);
        const int lrow0 = warp_m + rowg, lrow1 = lrow0 + 8;
        float s0 = 0.f, s1 = 0.f;
#pragma unroll
        for (int j = 0; j < 16; j++) {
            int col = j * 8 + colq;
            float e0 = fast_expf(acc[j][0] - nm0);
            float e1 = fast_expf(acc[j][1] - nm0);
            float e2 = fast_expf(acc[j][2] - nm1);
            float e3 = fast_expf(acc[j][3] - nm1);
            s0 += e0 + e1; s1 += e2 + e3;
            if (diag) {
                if (col     > lrow0) e0 = 0.f;
                if (col + 1 > lrow0) e1 = 0.f;
                if (col     > lrow1) e2 = 0.f;
                if (col + 1 > lrow1) e3 = 0.f;
            }
            acc[j][0] = e0; acc[j][1] = e1; acc[j][2] = e2; acc[j][3] = e3;
        }
        s0 += __shfl_xor_sync(0xFFFFFFFF, s0, 1);
        s0 += __shfl_xor_sync(0xFFFFFFFF, s0, 2);
        s1 += __shfl_xor_sync(0xFFFFFFFF, s1, 1);
        s1 += __shfl_xor_sync(0xFFFFFFFF, s1, 2);
        l0 = l0 * r0 + s0;
        l1 = l1 * r1 + s1;

        // rescale O
#pragma unroll
        for (int j = 0; j < 16; j++) {
            O[j][0] *= r0; O[j][1] *= r0; O[j][2] *= r1; O[j][3] *= r1;
        }

        // ---- PV (causal-skipped) ----
        if (kt <= qt) {
#pragma unroll
            for (int ks = 0; ks < 8; ks++) {
                uint32_t pah[4], pal[4];
                {
                    float x0 = acc[2 * ks][0], x1 = acc[2 * ks][1];
                    float x2 = acc[2 * ks][2], x3 = acc[2 * ks][3];
                    float y0 = acc[2 * ks + 1][0], y1 = acc[2 * ks + 1][1];
                    float y2 = acc[2 * ks + 1][2], y3 = acc[2 * ks + 1][3];
                    pah[0] = pack_bf2(x0, x1);
                    pah[1] = pack_bf2(x2, x3);
                    pah[2] = pack_bf2(y0, y1);
                    pah[3] = pack_bf2(y2, y3);
                    float hx0 = __bfloat162float(__float2bfloat16(x0));
                    float hx1 = __bfloat162float(__float2bfloat16(x1));
                    float hx2 = __bfloat162float(__float2bfloat16(x2));
                    float hx3 = __bfloat162float(__float2bfloat16(x3));
                    float hy0 = __bfloat162float(__float2bfloat16(y0));
                    float hy1 = __bfloat162float(__float2bfloat16(y1));
                    float hy2 = __bfloat162float(__float2bfloat16(y2));
                    float hy3 = __bfloat162float(__float2bfloat16(y3));
                    pal[0] = pack_bf2(x0 - hx0, x1 - hx1);
                    pal[1] = pack_bf2(x2 - hx2, x3 - hx3);
                    pal[2] = pack_bf2(y0 - hy0, y1 - hy1);
                    pal[3] = pack_bf2(y2 - hy2, y3 - hy3);
                }
#pragma unroll
                for (int pn = 0; pn < 8; pn++) {
                    uint32_t vh[4], vl[4];
                    int brow = pn * 16 + rB, bch = ks * 2 + hbB;
                    ldsm4(vh, smb + FVHI + tile256(brow, bch));
                    ldsm4(vl, smb + FVLO + tile256(brow, bch));
                    mma16816(O[2 * pn],     pah, vh[0], vh[1]);
                    mma16816(O[2 * pn],     pal, vh[0], vh[1]);
                    mma16816(O[2 * pn],     pah, vl[0], vl[1]);
                    mma16816(O[2 * pn + 1], pah, vh[2], vh[3]);
                    mma16816(O[2 * pn + 1], pal, vh[2], vh[3]);
                    mma16816(O[2 * pn + 1], pah, vl[2], vl[3]);
                }
            }
        }
    }

    // ---- epilogue: ctx = O/l - 1e9 * Suf ----
    const float inv0 = 1.f / l0, inv1 = 1.f / l1;
    const int grow0 = q0 + warp_m + rowg;
#pragma unroll
    for (int j = 0; j < 16; j++) {
        int d = j * 8 + colq;
        size_t o0 = base + (size_t)grow0 * D_ + d;
        size_t o1 = o0 + 8 * (size_t)D_;
        float2 sf0 = *(const float2*)(Suf + o0);
        float2 sf1 = *(const float2*)(Suf + o1);
        float2 w0 = {O[j][0] * inv0 - 1.0e9f * sf0.x,
                     O[j][1] * inv0 - 1.0e9f * sf0.y};
        float2 w1 = {O[j][2] * inv1 - 1.0e9f * sf1.x,
                     O[j][3] * inv1 - 1.0e9f * sf1.y};
        *(float2*)(ctx + o0) = w0;
        *(float2*)(ctx + o1) = w1;
    }
}

// ============================================================================
typedef CUresult (*PFN_encodeTiled)(
    CUtensorMap*, CUtensorMapDataType, cuuint32_t, void*,
    const cuuint64_t*, const cuuint64_t*, const cuuint32_t*, const cuuint32_t*,
    CUtensorMapInterleave, CUtensorMapSwizzle, CUtensorMapL2promotion,
    CUtensorMapFloatOOBfill);

static void make_map_bf16(PFN_encodeTiled enc, CUtensorMap* m, void* ptr,
                          unsigned long long rows)
{
    cuuint64_t dims[2] = {(cuuint64_t)Kd, (cuuint64_t)rows};
    cuuint64_t strides[1] = {(cuuint64_t)Kd * 2};
    cuuint32_t box[2] = {64, 128};
    cuuint32_t es[2] = {1, 1};
    enc(m, CU_TENSOR_MAP_DATA_TYPE_BFLOAT16, 2, ptr, dims, strides, box, es,
        CU_TENSOR_MAP_INTERLEAVE_NONE, CU_TENSOR_MAP_SWIZZLE_128B,
        CU_TENSOR_MAP_L2_PROMOTION_L2_128B, CU_TENSOR_MAP_FLOAT_OOB_FILL_NONE);
}

extern "C" void kernel_launch(void* const* d_in, const int* in_sizes, int n_in,
                              void* d_out, int out_size)
{
    const float* q  = (const float*)d_in[0];
    const float* k  = (const float*)d_in[1];
    const float* v  = (const float*)d_in[2];
    const float* Wq = (const float*)d_in[3];
    const float* bq = (const float*)d_in[4];
    const float* Wk = (const float*)d_in[5];
    const float* bk = (const float*)d_in[6];
    const float* Wv = (const float*)d_in[7];
    const float* bvv = (const float*)d_in[8];
    const float* Wo = (const float*)d_in[9];
    const float* bo = (const float*)d_in[10];
    float* out = (float*)d_out;
    (void)in_sizes; (void)n_in; (void)out_size;

    float *gQ, *gK, *gV, *gSuf, *gctx, *gcs;
    cudaGetSymbolAddress((void**)&gQ,   g_Q);
    cudaGetSymbolAddress((void**)&gK,   g_K);
    cudaGetSymbolAddress((void**)&gV,   g_V);
    cudaGetSymbolAddress((void**)&gSuf, g_Suf);
    cudaGetSymbolAddress((void**)&gctx, g_ctx);
    cudaGetSymbolAddress((void**)&gcs,  g_csum);
    __nv_bfloat16 *gAhi, *gAlo, *gWthi, *gWtlo;
    cudaGetSymbolAddress((void**)&gAhi, g_Ahi);
    cudaGetSymbolAddress((void**)&gAlo, g_Alo);
    cudaGetSymbolAddress((void**)&gWthi, g_Wthi);
    cudaGetSymbolAddress((void**)&gWtlo, g_Wtlo);

    void* pfn = nullptr;
    cudaDriverEntryPointQueryResult qr;
    cudaGetDriverEntryPointByVersion("cuTensorMapEncodeTiled", &pfn, 12000,
                                     cudaEnableDefault, &qr);
    PFN_encodeTiled enc = (PFN_encodeTiled)pfn;

    const int WN = D_ * D_;
    CUtensorMap mAhi, mAlo;
    CUtensorMap mWhi[4], mWlo[4];
    make_map_bf16(enc, &mAhi, gAhi, M_);
    make_map_bf16(enc, &mAlo, gAlo, M_);
    for (int i = 0; i < 4; i++) {
        make_map_bf16(enc, &mWhi[i], gWthi + (size_t)i * WN, Nd);
        make_map_bf16(enc, &mWlo[i], gWtlo + (size_t)i * WN, Nd);
    }

    cudaFuncSetAttribute(flash_mma, cudaFuncAttributeMaxDynamicSharedMemorySize,
                         FT_SMEM);
    cudaFuncSetAttribute(hgemm_bf16x3, cudaFuncAttributeMaxDynamicSharedMemorySize,
                         GM_SMEM);

    dim3 wg(64, 64);
    conv_wt<<<wg, 256>>>(Wq, gWthi + 0 * (size_t)WN, gWtlo + 0 * (size_t)WN);
    conv_wt<<<wg, 256>>>(Wk, gWthi + 1 * (size_t)WN, gWtlo + 1 * (size_t)WN);
    conv_wt<<<wg, 256>>>(Wv, gWthi + 2 * (size_t)WN, gWtlo + 2 * (size_t)WN);
    conv_wt<<<wg, 256>>>(Wo, gWthi + 3 * (size_t)WN, gWtlo + 3 * (size_t)WN);

    dim3 gg(Nd / GM_BN, M_ / GM_BM);  // (16, 64)
    const int NCV = M_ * D_ / 4 / 256;

    conv_split<<<NCV, 256>>>(q, gAhi, gAlo, M_ * D_);
    hgemm_bf16x3<<<gg, 256, GM_SMEM>>>(mAhi, mAlo, mWhi[0], mWlo[0], bq, gQ);
    conv_split<<<NCV, 256>>>(k, gAhi, gAlo, M_ * D_);
    hgemm_bf16x3<<<gg, 256, GM_SMEM>>>(mAhi, mAlo, mWhi[1], mWlo[1], bk, gK);
    conv_split<<<NCV, 256>>>(v, gAhi, gAlo, M_ * D_);
    hgemm_bf16x3<<<gg, 256, GM_SMEM>>>(mAhi, mAlo, mWhi[2], mWlo[2], bvv, gV);

    v_chunk_sum<<<Bb_ * H_ * 32, 128>>>(gV, gcs);
    v_suffix<<<Bb_ * H_ * 32, 128>>>(gV, gcs, gSuf);
    flash_mma<<<dim3(Bb_ * H_, 16), 256, FT_SMEM>>>(gQ, gK, gV, gSuf, gctx);

    conv_split<<<NCV, 256>>>(gctx, gAhi, gAlo, M_ * D_);
    hgemm_bf16x3<<<gg, 256, GM_SMEM>>>(mAhi, mAlo, mWhi[3], mWlo[3], bo, out);
}

// round 6
// speedup vs baseline: 5.7945x; 1.0467x over previous
#include <cuda_runtime.h>
#include <cuda_bf16.h>
#include <cuda.h>
#include <cstdint>

// Problem constants
constexpr int Bb_ = 4, S_ = 2048, D_ = 2048, H_ = 16, DH_ = 128;
constexpr int M_ = Bb_ * S_;  // 8192
constexpr int Kd = 2048, Nd = 2048;

// Scratch (static __device__ — no allocations allowed)
__device__ float g_Q[M_ * D_];
__device__ float g_K[M_ * D_];
__device__ float g_V[M_ * D_];
__device__ float g_Suf[M_ * D_];
__device__ float g_csum[Bb_ * H_ * 32 * DH_];
__device__ __nv_bfloat16 g_Ahi[M_ * D_];
__device__ __nv_bfloat16 g_Alo[M_ * D_];
__device__ __nv_bfloat16 g_Wthi[4][D_ * D_];
__device__ __nv_bfloat16 g_Wtlo[4][D_ * D_];
__device__ __nv_bfloat16 g_Khi[M_ * D_];
__device__ __nv_bfloat16 g_Klo[M_ * D_];
__device__ __nv_bfloat16 g_VThi[M_ * D_];   // [(b*H+h)*DH + d][s]
__device__ __nv_bfloat16 g_VTlo[M_ * D_];

#define DEV_INLINE __device__ __forceinline__

// ======================= PTX helpers (portable, non-"a") ====================
DEV_INLINE uint32_t s2u(const void* p) {
    uint32_t a;
    asm("{ .reg .u64 t; cvta.to.shared.u64 t, %1; cvt.u32.u64 %0, t; }"
        : "=r"(a) : "l"(p));
    return a;
}
DEV_INLINE void mbar_init(uint32_t a, uint32_t c) {
    asm volatile("mbarrier.init.shared.b64 [%0], %1;" :: "r"(a), "r"(c) : "memory");
}
DEV_INLINE void mbar_expect_tx(uint32_t a, uint32_t bytes) {
    asm volatile("mbarrier.arrive.expect_tx.shared.b64 _, [%0], %1;"
                 :: "r"(a), "r"(bytes) : "memory");
}
DEV_INLINE void mbar_wait(uint32_t a, uint32_t ph) {
    asm volatile(
        "{ .reg .pred P;\n\t"
        "WL%=:\n\t"
        "mbarrier.try_wait.parity.acquire.cta.shared::cta.b64 P, [%0], %1, 0x989680;\n\t"
        "@P bra WD%=;\n\t"
        "bra WL%=;\n\t"
        "WD%=: }\n\t"
        :: "r"(a), "r"(ph) : "memory");
}
DEV_INLINE void fence_mbar_init() {
    asm volatile("fence.mbarrier_init.release.cluster;" ::: "memory");
}
DEV_INLINE void tma2d(uint32_t dst, const void* map, int x, int y, uint32_t mbar) {
    asm volatile(
        "cp.async.bulk.tensor.2d.shared::cluster.global.tile.mbarrier::complete_tx::bytes "
        "[%0], [%1, {%2, %3}], [%4];"
        :: "r"(dst), "l"(map), "r"(x), "r"(y), "r"(mbar) : "memory");
}
DEV_INLINE void ldsm4(uint32_t (&r)[4], uint32_t addr) {
    asm volatile("ldmatrix.sync.aligned.m8n8.x4.shared.b16 {%0,%1,%2,%3}, [%4];"
                 : "=r"(r[0]), "=r"(r[1]), "=r"(r[2]), "=r"(r[3]) : "r"(addr));
}
DEV_INLINE void mma16816(float (&d)[4], const uint32_t (&a)[4], uint32_t b0, uint32_t b1) {
    asm volatile(
        "mma.sync.aligned.m16n8k16.row.col.f32.bf16.bf16.f32 "
        "{%0,%1,%2,%3}, {%4,%5,%6,%7}, {%8,%9}, {%0,%1,%2,%3};"
        : "+f"(d[0]), "+f"(d[1]), "+f"(d[2]), "+f"(d[3])
        : "r"(a[0]), "r"(a[1]), "r"(a[2]), "r"(a[3]), "r"(b0), "r"(b1));
}
DEV_INLINE void cpa16(uint32_t dst, const void* g) {
    asm volatile("cp.async.cg.shared.global [%0], [%1], 16;" :: "r"(dst), "l"(g) : "memory");
}
#define CP_COMMIT() asm volatile("cp.async.commit_group;" ::: "memory")
DEV_INLINE void cp_wait0() { asm volatile("cp.async.wait_group 0;" ::: "memory"); }

// FMA-only exp
DEV_INLINE float fast_expf(float x) {
    float t = x * 1.4426950408889634f;
    t = fmaxf(t, -126.0f);
    float n = floorf(t);
    float f = t - n;
    float r = 1.5495262e-4f;
    r = fmaf(r, f, 1.3333558e-3f);
    r = fmaf(r, f, 9.6181291e-3f);
    r = fmaf(r, f, 5.5504109e-2f);
    r = fmaf(r, f, 2.4022651e-1f);
    r = fmaf(r, f, 6.9314718e-1f);
    r = fmaf(r, f, 1.0f);
    float s = __int_as_float(((int)n + 127) << 23);
    return r * s;
}
DEV_INLINE uint32_t pack_bf2(float a, float b) {
    __nv_bfloat162 p = __halves2bfloat162(__float2bfloat16(a), __float2bfloat16(b));
    return *(uint32_t*)&p;
}

// ============================================================================
// Conversion kernels
// ============================================================================
__global__ __launch_bounds__(256)
void conv_split(const float* __restrict__ x, __nv_bfloat16* __restrict__ hi,
                __nv_bfloat16* __restrict__ lo, int n)
{
    int i = (blockIdx.x * 256 + threadIdx.x) * 4;
    if (i >= n) return;
    float4 v = *(const float4*)(x + i);
    __nv_bfloat16 h0 = __float2bfloat16(v.x);
    __nv_bfloat16 h1 = __float2bfloat16(v.y);
    __nv_bfloat16 h2 = __float2bfloat16(v.z);
    __nv_bfloat16 h3 = __float2bfloat16(v.w);
    *(__nv_bfloat162*)(hi + i)     = __halves2bfloat162(h0, h1);
    *(__nv_bfloat162*)(hi + i + 2) = __halves2bfloat162(h2, h3);
    __nv_bfloat16 l0 = __float2bfloat16(v.x - __bfloat162float(h0));
    __nv_bfloat16 l1 = __float2bfloat16(v.y - __bfloat162float(h1));
    __nv_bfloat16 l2 = __float2bfloat16(v.z - __bfloat162float(h2));
    __nv_bfloat16 l3 = __float2bfloat16(v.w - __bfloat162float(h3));
    *(__nv_bfloat162*)(lo + i)     = __halves2bfloat162(l0, l1);
    *(__nv_bfloat162*)(lo + i + 2) = __halves2bfloat162(l2, l3);
}

// W [K,N] fp32 -> Wt [N,K] bf16 hi/lo (transpose + split)
__global__ __launch_bounds__(256)
void conv_wt(const float* __restrict__ W, __nv_bfloat16* __restrict__ Thi,
             __nv_bfloat16* __restrict__ Tlo)
{
    __shared__ float t[32][33];
    int n0 = blockIdx.x * 32, k0 = blockIdx.y * 32;
    int tx = threadIdx.x & 31, ty = threadIdx.x >> 5;
    for (int r = ty; r < 32; r += 8)
        t[r][tx] = W[(size_t)(k0 + r) * Nd + n0 + tx];
    __syncthreads();
    for (int r = ty; r < 32; r += 8) {
        float x = t[tx][r];
        __nv_bfloat16 h = __float2bfloat16(x);
        Thi[(size_t)(n0 + r) * Kd + k0 + tx] = h;
        Tlo[(size_t)(n0 + r) * Kd + k0 + tx] =
            __float2bfloat16(x - __bfloat162float(h));
    }
}

// V [B,S,D] fp32 -> VT [(b*H+h)*DH + d][s] bf16 hi/lo (per-head transpose+split)
__global__ __launch_bounds__(256)
void conv_vt(const float* __restrict__ V, __nv_bfloat16* __restrict__ Thi,
             __nv_bfloat16* __restrict__ Tlo)
{
    __shared__ float t[32][33];
    int s0 = blockIdx.x * 32;
    int r0 = blockIdx.y * 32;             // global VT row = (b*H+h)*DH + d
    int bh = r0 >> 7;                     // DH=128
    int d0 = r0 & 127;
    int b = bh >> 4, h = bh & 15;
    int tx = threadIdx.x & 31, ty = threadIdx.x >> 5;
    const float* src = V + (size_t)b * S_ * D_ + h * DH_ + d0;
    for (int r = ty; r < 32; r += 8)
        t[r][tx] = src[(size_t)(s0 + r) * D_ + tx];
    __syncthreads();
    for (int r = ty; r < 32; r += 8) {
        float x = t[tx][r];               // V[s0+tx, d0+r]
        __nv_bfloat16 hh = __float2bfloat16(x);
        size_t o = (size_t)(r0 + r) * S_ + s0 + tx;
        Thi[o] = hh;
        Tlo[o] = __float2bfloat16(x - __bfloat162float(hh));
    }
}

// ============================================================================
// HMMA bf16x3 GEMM (validated round 4)
// ============================================================================
constexpr int GM_BM = 128, GM_BN = 128, GM_BK = 64;
constexpr int OFF_AHI = 0, OFF_ALO = 16384, OFF_BHI = 32768, OFF_BLO = 49152;
constexpr int STG_SZ = 65536;
constexpr int GM_SMEM = 1024 + 2 * STG_SZ + 64;

DEV_INLINE uint32_t tile_off(int r, int c) {
    return (uint32_t)(r * 128 + ((c ^ (r & 7)) << 4));
}
// 128-row x 256B logical tile as two stacked 16KB SW128 subtiles, chunk c 0..15
DEV_INLINE uint32_t tileKs(int r, int c) {
    return (uint32_t)((c >> 3) * 16384) + tile_off(r, c & 7);
}

__global__ __launch_bounds__(256, 1)
void hgemm_bf16x3(const __grid_constant__ CUtensorMap mAhi,
                  const __grid_constant__ CUtensorMap mAlo,
                  const __grid_constant__ CUtensorMap mBhi,
                  const __grid_constant__ CUtensorMap mBlo,
                  const float* __restrict__ bias, float* __restrict__ C)
{
    extern __shared__ char smraw[];
    uint32_t smb = (s2u(smraw) + 1023u) & ~1023u;
    const uint32_t full0 = smb + 2 * STG_SZ;
    const uint32_t full1 = full0 + 8;

    const int tid = threadIdx.x;
    const int wid = tid >> 5, lane = tid & 31;
    const int m0 = blockIdx.y * GM_BM;
    const int n0 = blockIdx.x * GM_BN;
    const int warp_m = (wid & 3) * 32;
    const int warp_n = (wid >> 2) * 64;

    if (tid == 0) {
        mbar_init(full0, 1);
        mbar_init(full1, 1);
        fence_mbar_init();
    }
    __syncthreads();

    const int mat = lane >> 3, l7 = lane & 7;
    const int hbA = mat >> 1;
    const int rA = ((mat & 1) << 3) + l7;
    const int hbB = mat & 1;
    const int rB = ((mat >> 1) << 3) + l7;

    float acc[2][8][4];
#pragma unroll
    for (int i = 0; i < 2; i++)
#pragma unroll
        for (int j = 0; j < 8; j++)
#pragma unroll
            for (int q = 0; q < 4; q++) acc[i][j][q] = 0.f;

    if (tid == 0) {
        mbar_expect_tx(full0, 4 * 16384);
        tma2d(smb + OFF_AHI, &mAhi, 0, m0, full0);
        tma2d(smb + OFF_ALO, &mAlo, 0, m0, full0);
        tma2d(smb + OFF_BHI, &mBhi, 0, n0, full0);
        tma2d(smb + OFF_BLO, &mBlo, 0, n0, full0);
    }

    const int NCH = Kd / GM_BK;
    for (int c = 0; c < NCH; c++) {
        const int s = c & 1;
        const uint32_t sb = smb + s * STG_SZ;
        mbar_wait(s == 0 ? full0 : full1, (c >> 1) & 1);
        if (tid == 0 && c + 1 < NCH) {
            const uint32_t sb2 = smb + (s ^ 1) * STG_SZ;
            const uint32_t fb2 = (s == 0) ? full1 : full0;
            mbar_expect_tx(fb2, 4 * 16384);
            int kx = (c + 1) * GM_BK;
            tma2d(sb2 + OFF_AHI, &mAhi, kx, m0, fb2);
            tma2d(sb2 + OFF_ALO, &mAlo, kx, m0, fb2);
            tma2d(sb2 + OFF_BHI, &mBhi, kx, n0, fb2);
            tma2d(sb2 + OFF_BLO, &mBlo, kx, n0, fb2);
        }

#pragma unroll
        for (int ks = 0; ks < 4; ks++) {
            uint32_t ah[2][4], al[2][4], bh[4][4], bl[4][4];
#pragma unroll
            for (int im = 0; im < 2; im++) {
                int row = warp_m + im * 16 + rA;
                int ch = ks * 2 + hbA;
                ldsm4(ah[im], sb + OFF_AHI + tile_off(row, ch));
                ldsm4(al[im], sb + OFF_ALO + tile_off(row, ch));
            }
#pragma unroll
            for (int p = 0; p < 4; p++) {
                int row = warp_n + p * 16 + rB;
                int ch = ks * 2 + hbB;
                ldsm4(bh[p], sb + OFF_BHI + tile_off(row, ch));
                ldsm4(bl[p], sb + OFF_BLO + tile_off(row, ch));
            }
#pragma unroll
            for (int im = 0; im < 2; im++)
#pragma unroll
                for (int p = 0; p < 4; p++) {
                    mma16816(acc[im][2 * p],     ah[im], bh[p][0], bh[p][1]);
                    mma16816(acc[im][2 * p],     ah[im], bl[p][0], bl[p][1]);
                    mma16816(acc[im][2 * p],     al[im], bh[p][0], bh[p][1]);
                    mma16816(acc[im][2 * p + 1], ah[im], bh[p][2], bh[p][3]);
                    mma16816(acc[im][2 * p + 1], ah[im], bl[p][2], bl[p][3]);
                    mma16816(acc[im][2 * p + 1], al[im], bh[p][2], bh[p][3]);
                }
        }
        __syncthreads();
    }

    const int rowg = lane >> 2, colg = (lane & 3) * 2;
#pragma unroll
    for (int im = 0; im < 2; im++) {
#pragma unroll
        for (int jn = 0; jn < 8; jn++) {
            int n = n0 + warp_n + jn * 8 + colg;
            float2 bv = *(const float2*)(bias + n);
            size_t r0 = (size_t)(m0 + warp_m + im * 16 + rowg) * Nd + n;
            float2 v0 = {acc[im][jn][0] + bv.x, acc[im][jn][1] + bv.y};
            *(float2*)(C + r0) = v0;
            float2 v1 = {acc[im][jn][2] + bv.x, acc[im][jn][3] + bv.y};
            *(float2*)(C + r0 + 8 * Nd) = v1;
        }
    }
}

// ============================================================================
// Suffix-sum of V per (b,h)
// ============================================================================
__global__ __launch_bounds__(128)
void v_chunk_sum(const float* __restrict__ V, float* __restrict__ cs)
{
    int idx = blockIdx.x;
    int c = idx & 31;
    int h = (idx >> 5) & 15;
    int b = idx >> 9;
    int d = threadIdx.x;
    size_t base = ((size_t)b * S_ + c * 64) * D_ + h * DH_ + d;
    float s = 0.f;
    for (int r = 0; r < 64; r++) s += V[base + (size_t)r * D_];
    cs[(size_t)idx * DH_ + d] = s;
}

__global__ __launch_bounds__(128)
void v_suffix(const float* __restrict__ V, const float* __restrict__ cs,
              float* __restrict__ Suf)
{
    int idx = blockIdx.x;
    int c = idx & 31;
    int h = (idx >> 5) & 15;
    int b = idx >> 9;
    int d = threadIdx.x;
    int bh = idx >> 5;
    float acc = 0.f;
    for (int c2 = c + 1; c2 < 32; c2++) acc += cs[((size_t)bh * 32 + c2) * DH_ + d];
    size_t base = ((size_t)b * S_ + c * 64) * D_ + h * DH_ + d;
    for (int r = 63; r >= 0; r--) {
        Suf[base + (size_t)r * D_] = acc;
        acc += V[base + (size_t)r * D_];
    }
}

// ============================================================================
// Flash attention v3: precision-adaptive HMMA.
// Fast path (qt<15): single-bf16 QK and PV — their error is invisible behind
// the -1e9*Suf term that dominates every row except q=S-1.
// Precise path (qt==15): bf16x3 both. Full-row softmax stats, mask gates PV.
// K/VT pre-split in global; cp.async tile loads. Epilogue writes bf16 hi/lo
// splits of ctx directly (consumed by the Wo GEMM).
// ============================================================================
constexpr int FT_SMEM = 6 * 32768;
constexpr int FQHI = 0, FQLO = 32768, FKHI = 65536, FKLO = 98304,
              FVHI = 131072, FVLO = 163840;

__global__ __launch_bounds__(256, 1)
void flash_mma(const float* __restrict__ Qp,
               const __nv_bfloat16* __restrict__ Khi,
               const __nv_bfloat16* __restrict__ Klo,
               const __nv_bfloat16* __restrict__ VThi,
               const __nv_bfloat16* __restrict__ VTlo,
               const float* __restrict__ Suf,
               __nv_bfloat16* __restrict__ ctx_hi,
               __nv_bfloat16* __restrict__ ctx_lo)
{
    extern __shared__ char fsm[];
    const uint32_t smb = s2u(fsm);
    const int tid = threadIdx.x, wid = tid >> 5, lane = tid & 31;
    const int bh = blockIdx.x, qt = blockIdx.y;
    const int b = bh >> 4, h = bh & 15;
    const size_t base = (size_t)b * S_ * D_ + h * DH_;
    const int q0 = qt * 128;
    const bool precise = (qt == 15);

    const int mat = lane >> 3, l7 = lane & 7;
    const int hbA = mat >> 1, rA = ((mat & 1) << 3) + l7;
    const int hbB = mat & 1, rB = ((mat >> 1) << 3) + l7;
    const int rowg = lane >> 2, colq = (lane & 3) * 2;
    const int warp_m = wid * 16;

    // ---- load & convert Q tile (once) ----
#pragma unroll
    for (int i = 0; i < 16; i++) {
        int idx = i * 256 + tid;
        int r = idx >> 5, c4 = (idx & 31) * 4;
        float4 v = *(const float4*)(Qp + base + (size_t)(q0 + r) * D_ + c4);
        uint32_t off = tileKs(r, c4 >> 3) + (c4 & 4) * 2;
        *(uint2*)(fsm + FQHI + off) = make_uint2(pack_bf2(v.x, v.y), pack_bf2(v.z, v.w));
        float hx = __bfloat162float(__float2bfloat16(v.x));
        float hy = __bfloat162float(__float2bfloat16(v.y));
        float hz = __bfloat162float(__float2bfloat16(v.z));
        float hw = __bfloat162float(__float2bfloat16(v.w));
        *(uint2*)(fsm + FQLO + off) =
            make_uint2(pack_bf2(v.x - hx, v.y - hy), pack_bf2(v.z - hz, v.w - hw));
    }

    float O[16][4];
#pragma unroll
    for (int j = 0; j < 16; j++)
#pragma unroll
        for (int q = 0; q < 4; q++) O[j][q] = 0.f;
    float m0 = -3.0e38f, m1 = -3.0e38f, l0 = 0.f, l1 = 0.f;

    // global row bases for the tile loads
    const __nv_bfloat16* Kh_b = Khi + base;              // row stride D_
    const __nv_bfloat16* Kl_b = Klo + base;
    const __nv_bfloat16* Vh_b = VThi + (size_t)bh * DH_ * S_;  // row stride S_
    const __nv_bfloat16* Vl_b = VTlo + (size_t)bh * DH_ * S_;

    for (int kt = 0; kt < 16; kt++) {
        const int k0 = kt * 128;
        __syncthreads();  // previous tile fully consumed
        // ---- cp.async tile loads: 2048 16B chunks per 32KB tile ----
#pragma unroll
        for (int i = 0; i < 8; i++) {
            int idx = i * 256 + tid;
            int r = idx >> 4, c = idx & 15;
            uint32_t so = tileKs(r, c);
            cpa16(smb + FKHI + so, Kh_b + (size_t)(k0 + r) * D_ + c * 8);
            cpa16(smb + FVHI + so, Vh_b + (size_t)r * S_ + k0 + c * 8);
        }
        if (precise) {
#pragma unroll
            for (int i = 0; i < 8; i++) {
                int idx = i * 256 + tid;
                int r = idx >> 4, c = idx & 15;
                uint32_t so = tileKs(r, c);
                cpa16(smb + FKLO + so, Kl_b + (size_t)(k0 + r) * D_ + c * 8);
                cpa16(smb + FVLO + so, Vl_b + (size_t)r * S_ + k0 + c * 8);
            }
        }
        CP_COMMIT();
        cp_wait0();
        __syncthreads();

        // ---- S = Q K^T ----
        float acc[16][4];
#pragma unroll
        for (int j = 0; j < 16; j++)
#pragma unroll
            for (int q = 0; q < 4; q++) acc[j][q] = 0.f;
#pragma unroll
        for (int ks = 0; ks < 8; ks++) {
            uint32_t ah[4], al[4];
            int arow = warp_m + rA, ach = ks * 2 + hbA;
            ldsm4(ah, smb + FQHI + tileKs(arow, ach));
            if (precise) ldsm4(al, smb + FQLO + tileKs(arow, ach));
#pragma unroll
            for (int p = 0; p < 8; p++) {
                uint32_t bhf[4];
                int brow = p * 16 + rB, bch = ks * 2 + hbB;
                ldsm4(bhf, smb + FKHI + tileKs(brow, bch));
                mma16816(acc[2 * p],     ah, bhf[0], bhf[1]);
                mma16816(acc[2 * p + 1], ah, bhf[2], bhf[3]);
                if (precise) {
                    uint32_t blf[4];
                    ldsm4(blf, smb + FKLO + tileKs(brow, bch));
                    mma16816(acc[2 * p],     al, bhf[0], bhf[1]);
                    mma16816(acc[2 * p],     ah, blf[0], blf[1]);
                    mma16816(acc[2 * p + 1], al, bhf[2], bhf[3]);
                    mma16816(acc[2 * p + 1], ah, blf[2], blf[3]);
                }
            }
        }
#pragma unroll
        for (int j = 0; j < 16; j++)
#pragma unroll
            for (int q = 0; q < 4; q++) acc[j][q] *= 0.08838834764831845f;

        // ---- online softmax (full-row stats) ----
        float mx0 = -3.0e38f, mx1 = -3.0e38f;
#pragma unroll
        for (int j = 0; j < 16; j++) {
            mx0 = fmaxf(mx0, fmaxf(acc[j][0], acc[j][1]));
            mx1 = fmaxf(mx1, fmaxf(acc[j][2], acc[j][3]));
        }
        mx0 = fmaxf(mx0, __shfl_xor_sync(0xFFFFFFFF, mx0, 1));
        mx0 = fmaxf(mx0, __shfl_xor_sync(0xFFFFFFFF, mx0, 2));
        mx1 = fmaxf(mx1, __shfl_xor_sync(0xFFFFFFFF, mx1, 1));
        mx1 = fmaxf(mx1, __shfl_xor_sync(0xFFFFFFFF, mx1, 2));
        float nm0 = fmaxf(m0, mx0), nm1 = fmaxf(m1, mx1);
        float r0 = fast_expf(m0 - nm0), r1 = fast_expf(m1 - nm1);
        m0 = nm0; m1 = nm1;

        const bool diag = (kt == qt);
        const int lrow0 = warp_m + rowg, lrow1 = lrow0 + 8;
        float s0 = 0.f, s1 = 0.f;
#pragma unroll
        for (int j = 0; j < 16; j++) {
            int col = j * 8 + colq;
            float e0 = fast_expf(acc[j][0] - nm0);
            float e1 = fast_expf(acc[j][1] - nm0);
            float e2 = fast_expf(acc[j][2] - nm1);
            float e3 = fast_expf(acc[j][3] - nm1);
            s0 += e0 + e1; s1 += e2 + e3;
            if (diag) {
                if (col     > lrow0) e0 = 0.f;
                if (col + 1 > lrow0) e1 = 0.f;
                if (col     > lrow1) e2 = 0.f;
                if (col + 1 > lrow1) e3 = 0.f;
            }
            acc[j][0] = e0; acc[j][1] = e1; acc[j][2] = e2; acc[j][3] = e3;
        }
        s0 += __shfl_xor_sync(0xFFFFFFFF, s0, 1);
        s0 += __shfl_xor_sync(0xFFFFFFFF, s0, 2);
        s1 += __shfl_xor_sync(0xFFFFFFFF, s1, 1);
        s1 += __shfl_xor_sync(0xFFFFFFFF, s1, 2);
        l0 = l0 * r0 + s0;
        l1 = l1 * r1 + s1;

#pragma unroll
        for (int j = 0; j < 16; j++) {
            O[j][0] *= r0; O[j][1] *= r0; O[j][2] *= r1; O[j][3] *= r1;
        }

        // ---- PV (causal-skipped) ----
        if (kt <= qt) {
#pragma unroll
            for (int ks = 0; ks < 8; ks++) {
                uint32_t pah[4], pal[4];
                {
                    float x0 = acc[2 * ks][0], x1 = acc[2 * ks][1];
                    float x2 = acc[2 * ks][2], x3 = acc[2 * ks][3];
                    float y0 = acc[2 * ks + 1][0], y1 = acc[2 * ks + 1][1];
                    float y2 = acc[2 * ks + 1][2], y3 = acc[2 * ks + 1][3];
                    pah[0] = pack_bf2(x0, x1);
                    pah[1] = pack_bf2(x2, x3);
                    pah[2] = pack_bf2(y0, y1);
                    pah[3] = pack_bf2(y2, y3);
                    if (precise) {
                        float hx0 = __bfloat162float(__float2bfloat16(x0));
                        float hx1 = __bfloat162float(__float2bfloat16(x1));
                        float hx2 = __bfloat162float(__float2bfloat16(x2));
                        float hx3 = __bfloat162float(__float2bfloat16(x3));
                        float hy0 = __bfloat162float(__float2bfloat16(y0));
                        float hy1 = __bfloat162float(__float2bfloat16(y1));
                        float hy2 = __bfloat162float(__float2bfloat16(y2));
                        float hy3 = __bfloat162float(__float2bfloat16(y3));
                        pal[0] = pack_bf2(x0 - hx0, x1 - hx1);
                        pal[1] = pack_bf2(x2 - hx2, x3 - hx3);
                        pal[2] = pack_bf2(y0 - hy0, y1 - hy1);
                        pal[3] = pack_bf2(y2 - hy2, y3 - hy3);
                    }
                }
#pragma unroll
                for (int pn = 0; pn < 8; pn++) {
                    uint32_t vh[4];
                    int brow = pn * 16 + rB, bch = ks * 2 + hbB;
                    ldsm4(vh, smb + FVHI + tileKs(brow, bch));
                    mma16816(O[2 * pn],     pah, vh[0], vh[1]);
                    mma16816(O[2 * pn + 1], pah, vh[2], vh[3]);
                    if (precise) {
                        uint32_t vl[4];
                        ldsm4(vl, smb + FVLO + tileKs(brow, bch));
                        mma16816(O[2 * pn],     pal, vh[0], vh[1]);
                        mma16816(O[2 * pn],     pah, vl[0], vl[1]);
                        mma16816(O[2 * pn + 1], pal, vh[2], vh[3]);
                        mma16816(O[2 * pn + 1], pah, vl[2], vl[3]);
                    }
                }
            }
        }
    }

    // ---- epilogue: w = O/l - 1e9*Suf, write bf16 hi/lo splits ----
    const float inv0 = 1.f / l0, inv1 = 1.f / l1;
    const int grow0 = q0 + warp_m + rowg;
#pragma unroll
    for (int j = 0; j < 16; j++) {
        int d = j * 8 + colq;
        size_t o0 = base + (size_t)grow0 * D_ + d;
        size_t o1 = o0 + 8 * (size_t)D_;
        float2 sf0 = *(const float2*)(Suf + o0);
        float2 sf1 = *(const float2*)(Suf + o1);
        float w0x = fmaf(-1.0e9f, sf0.x, O[j][0] * inv0);
        float w0y = fmaf(-1.0e9f, sf0.y, O[j][1] * inv0);
        float w1x = fmaf(-1.0e9f, sf1.x, O[j][2] * inv1);
        float w1y = fmaf(-1.0e9f, sf1.y, O[j][3] * inv1);
        *(uint32_t*)(ctx_hi + o0) = pack_bf2(w0x, w0y);
        *(uint32_t*)(ctx_hi + o1) = pack_bf2(w1x, w1y);
        float h0x = __bfloat162float(__float2bfloat16(w0x));
        float h0y = __bfloat162float(__float2bfloat16(w0y));
        float h1x = __bfloat162float(__float2bfloat16(w1x));
        float h1y = __bfloat162float(__float2bfloat16(w1y));
        *(uint32_t*)(ctx_lo + o0) = pack_bf2(w0x - h0x, w0y - h0y);
        *(uint32_t*)(ctx_lo + o1) = pack_bf2(w1x - h1x, w1y - h1y);
    }
}

// ============================================================================
typedef CUresult (*PFN_encodeTiled)(
    CUtensorMap*, CUtensorMapDataType, cuuint32_t, void*,
    const cuuint64_t*, const cuuint64_t*, const cuuint32_t*, const cuuint32_t*,
    CUtensorMapInterleave, CUtensorMapSwizzle, CUtensorMapL2promotion,
    CUtensorMapFloatOOBfill);

static void make_map_bf16(PFN_encodeTiled enc, CUtensorMap* m, void* ptr,
                          unsigned long long rows)
{
    cuuint64_t dims[2] = {(cuuint64_t)Kd, (cuuint64_t)rows};
    cuuint64_t strides[1] = {(cuuint64_t)Kd * 2};
    cuuint32_t box[2] = {64, 128};
    cuuint32_t es[2] = {1, 1};
    enc(m, CU_TENSOR_MAP_DATA_TYPE_BFLOAT16, 2, ptr, dims, strides, box, es,
        CU_TENSOR_MAP_INTERLEAVE_NONE, CU_TENSOR_MAP_SWIZZLE_128B,
        CU_TENSOR_MAP_L2_PROMOTION_L2_128B, CU_TENSOR_MAP_FLOAT_OOB_FILL_NONE);
}

extern "C" void kernel_launch(void* const* d_in, const int* in_sizes, int n_in,
                              void* d_out, int out_size)
{
    const float* q  = (const float*)d_in[0];
    const float* k  = (const float*)d_in[1];
    const float* v  = (const float*)d_in[2];
    const float* Wq = (const float*)d_in[3];
    const float* bq = (const float*)d_in[4];
    const float* Wk = (const float*)d_in[5];
    const float* bk = (const float*)d_in[6];
    const float* Wv = (const float*)d_in[7];
    const float* bvv = (const float*)d_in[8];
    const float* Wo = (const float*)d_in[9];
    const float* bo = (const float*)d_in[10];
    float* out = (float*)d_out;
    (void)in_sizes; (void)n_in; (void)out_size;

    float *gQ, *gK, *gV, *gSuf, *gcs;
    cudaGetSymbolAddress((void**)&gQ,   g_Q);
    cudaGetSymbolAddress((void**)&gK,   g_K);
    cudaGetSymbolAddress((void**)&gV,   g_V);
    cudaGetSymbolAddress((void**)&gSuf, g_Suf);
    cudaGetSymbolAddress((void**)&gcs,  g_csum);
    __nv_bfloat16 *gAhi, *gAlo, *gWthi, *gWtlo, *gKhi, *gKlo, *gVThi, *gVTlo;
    cudaGetSymbolAddress((void**)&gAhi, g_Ahi);
    cudaGetSymbolAddress((void**)&gAlo, g_Alo);
    cudaGetSymbolAddress((void**)&gWthi, g_Wthi);
    cudaGetSymbolAddress((void**)&gWtlo, g_Wtlo);
    cudaGetSymbolAddress((void**)&gKhi, g_Khi);
    cudaGetSymbolAddress((void**)&gKlo, g_Klo);
    cudaGetSymbolAddress((void**)&gVThi, g_VThi);
    cudaGetSymbolAddress((void**)&gVTlo, g_VTlo);

    void* pfn = nullptr;
    cudaDriverEntryPointQueryResult qr;
    cudaGetDriverEntryPointByVersion("cuTensorMapEncodeTiled", &pfn, 12000,
                                     cudaEnableDefault, &qr);
    PFN_encodeTiled enc = (PFN_encodeTiled)pfn;

    const int WN = D_ * D_;
    CUtensorMap mAhi, mAlo;
    CUtensorMap mWhi[4], mWlo[4];
    make_map_bf16(enc, &mAhi, gAhi, M_);
    make_map_bf16(enc, &mAlo, gAlo, M_);
    for (int i = 0; i < 4; i++) {
        make_map_bf16(enc, &mWhi[i], gWthi + (size_t)i * WN, Nd);
        make_map_bf16(enc, &mWlo[i], gWtlo + (size_t)i * WN, Nd);
    }

    cudaFuncSetAttribute(flash_mma, cudaFuncAttributeMaxDynamicSharedMemorySize,
                         FT_SMEM);
    cudaFuncSetAttribute(hgemm_bf16x3, cudaFuncAttributeMaxDynamicSharedMemorySize,
                         GM_SMEM);

    dim3 wg(64, 64);
    conv_wt<<<wg, 256>>>(Wq, gWthi + 0 * (size_t)WN, gWtlo + 0 * (size_t)WN);
    conv_wt<<<wg, 256>>>(Wk, gWthi + 1 * (size_t)WN, gWtlo + 1 * (size_t)WN);
    conv_wt<<<wg, 256>>>(Wv, gWthi + 2 * (size_t)WN, gWtlo + 2 * (size_t)WN);
    conv_wt<<<wg, 256>>>(Wo, gWthi + 3 * (size_t)WN, gWtlo + 3 * (size_t)WN);

    dim3 gg(Nd / GM_BN, M_ / GM_BM);  // (16, 64)
    const int NCV = M_ * D_ / 4 / 256;

    conv_split<<<NCV, 256>>>(q, gAhi, gAlo, M_ * D_);
    hgemm_bf16x3<<<gg, 256, GM_SMEM>>>(mAhi, mAlo, mWhi[0], mWlo[0], bq, gQ);
    conv_split<<<NCV, 256>>>(k, gAhi, gAlo, M_ * D_);
    hgemm_bf16x3<<<gg, 256, GM_SMEM>>>(mAhi, mAlo, mWhi[1], mWlo[1], bk, gK);
    conv_split<<<NCV, 256>>>(v, gAhi, gAlo, M_ * D_);
    hgemm_bf16x3<<<gg, 256, GM_SMEM>>>(mAhi, mAlo, mWhi[2], mWlo[2], bvv, gV);

    // pre-split K and transposed V for flash
    conv_split<<<NCV, 256>>>(gK, gKhi, gKlo, M_ * D_);
    conv_vt<<<dim3(S_ / 32, M_ / 32), 256>>>(gV, gVThi, gVTlo);

    v_chunk_sum<<<Bb_ * H_ * 32, 128>>>(gV, gcs);
    v_suffix<<<Bb_ * H_ * 32, 128>>>(gV, gcs, gSuf);
    flash_mma<<<dim3(Bb_ * H_, 16), 256, FT_SMEM>>>(gQ, gKhi, gKlo, gVThi, gVTlo,
                                                    gSuf, gAhi, gAlo);

    hgemm_bf16x3<<<gg, 256, GM_SMEM>>>(mAhi, mAlo, mWhi[3], mWlo[3], bo, out);
}

// round 7
// speedup vs baseline: 6.8823x; 1.1877x over previous
#include <cuda_runtime.h>
#include <cuda_bf16.h>
#include <cuda.h>
#include <cstdint>

// Problem constants
constexpr int Bb_ = 4, S_ = 2048, D_ = 2048, H_ = 16, DH_ = 128;
constexpr int M_ = Bb_ * S_;  // 8192
constexpr int Kd = 2048, Nd = 2048;

// Scratch (static __device__ — no allocations allowed)
__device__ float g_Q[M_ * D_];
__device__ float g_K[M_ * D_];
__device__ float g_V[M_ * D_];
__device__ float g_Suf[M_ * D_];
__device__ float g_csum[Bb_ * H_ * 32 * DH_];
__device__ __nv_bfloat16 g_Ahi[M_ * D_];
__device__ __nv_bfloat16 g_Alo[M_ * D_];
__device__ __nv_bfloat16 g_Wthi[4][D_ * D_];
__device__ __nv_bfloat16 g_Wtlo[4][D_ * D_];
__device__ __nv_bfloat16 g_Khi[M_ * D_];
__device__ __nv_bfloat16 g_Klo[M_ * D_];
__device__ __nv_bfloat16 g_VThi[M_ * D_];   // [(b*H+h)*DH + d][s]
__device__ __nv_bfloat16 g_VTlo[M_ * D_];

#define DEV_INLINE __device__ __forceinline__

// ======================= PTX helpers (portable, non-"a") ====================
DEV_INLINE uint32_t s2u(const void* p) {
    uint32_t a;
    asm("{ .reg .u64 t; cvta.to.shared.u64 t, %1; cvt.u32.u64 %0, t; }"
        : "=r"(a) : "l"(p));
    return a;
}
DEV_INLINE void mbar_init(uint32_t a, uint32_t c) {
    asm volatile("mbarrier.init.shared.b64 [%0], %1;" :: "r"(a), "r"(c) : "memory");
}
DEV_INLINE void mbar_expect_tx(uint32_t a, uint32_t bytes) {
    asm volatile("mbarrier.arrive.expect_tx.shared.b64 _, [%0], %1;"
                 :: "r"(a), "r"(bytes) : "memory");
}
DEV_INLINE void mbar_wait(uint32_t a, uint32_t ph) {
    asm volatile(
        "{ .reg .pred P;\n\t"
        "WL%=:\n\t"
        "mbarrier.try_wait.parity.acquire.cta.shared::cta.b64 P, [%0], %1, 0x989680;\n\t"
        "@P bra WD%=;\n\t"
        "bra WL%=;\n\t"
        "WD%=: }\n\t"
        :: "r"(a), "r"(ph) : "memory");
}
DEV_INLINE void fence_mbar_init() {
    asm volatile("fence.mbarrier_init.release.cluster;" ::: "memory");
}
DEV_INLINE void tma2d(uint32_t dst, const void* map, int x, int y, uint32_t mbar) {
    asm volatile(
        "cp.async.bulk.tensor.2d.shared::cluster.global.tile.mbarrier::complete_tx::bytes "
        "[%0], [%1, {%2, %3}], [%4];"
        :: "r"(dst), "l"(map), "r"(x), "r"(y), "r"(mbar) : "memory");
}
DEV_INLINE void ldsm4(uint32_t (&r)[4], uint32_t addr) {
    asm volatile("ldmatrix.sync.aligned.m8n8.x4.shared.b16 {%0,%1,%2,%3}, [%4];"
                 : "=r"(r[0]), "=r"(r[1]), "=r"(r[2]), "=r"(r[3]) : "r"(addr));
}
DEV_INLINE void mma16816(float (&d)[4], const uint32_t (&a)[4], uint32_t b0, uint32_t b1) {
    asm volatile(
        "mma.sync.aligned.m16n8k16.row.col.f32.bf16.bf16.f32 "
        "{%0,%1,%2,%3}, {%4,%5,%6,%7}, {%8,%9}, {%0,%1,%2,%3};"
        : "+f"(d[0]), "+f"(d[1]), "+f"(d[2]), "+f"(d[3])
        : "r"(a[0]), "r"(a[1]), "r"(a[2]), "r"(a[3]), "r"(b0), "r"(b1));
}
DEV_INLINE void cpa16(uint32_t dst, const void* g) {
    asm volatile("cp.async.cg.shared.global [%0], [%1], 16;" :: "r"(dst), "l"(g) : "memory");
}
#define CP_COMMIT() asm volatile("cp.async.commit_group;" ::: "memory")
DEV_INLINE void cp_wait1() { asm volatile("cp.async.wait_group 1;" ::: "memory"); }
DEV_INLINE void cp_wait0() { asm volatile("cp.async.wait_group 0;" ::: "memory"); }

// MUFU exp2 (softmax runs in log2 domain; scale*log2e folded into Q)
DEV_INLINE float ex2f(float x) {
    float y;
    asm("ex2.approx.ftz.f32 %0, %1;" : "=f"(y) : "f"(x));
    return y;
}
DEV_INLINE uint32_t pack_bf2(float a, float b) {
    __nv_bfloat162 p = __halves2bfloat162(__float2bfloat16(a), __float2bfloat16(b));
    return *(uint32_t*)&p;
}

constexpr float SCL2 = 0.08838834764831845f * 1.4426950408889634f;

// ============================================================================
// Conversion kernels
// ============================================================================
__global__ __launch_bounds__(256)
void conv_split(const float* __restrict__ x, __nv_bfloat16* __restrict__ hi,
                __nv_bfloat16* __restrict__ lo, int n)
{
    int i = (blockIdx.x * 256 + threadIdx.x) * 4;
    if (i >= n) return;
    float4 v = *(const float4*)(x + i);
    __nv_bfloat16 h0 = __float2bfloat16(v.x);
    __nv_bfloat16 h1 = __float2bfloat16(v.y);
    __nv_bfloat16 h2 = __float2bfloat16(v.z);
    __nv_bfloat16 h3 = __float2bfloat16(v.w);
    *(__nv_bfloat162*)(hi + i)     = __halves2bfloat162(h0, h1);
    *(__nv_bfloat162*)(hi + i + 2) = __halves2bfloat162(h2, h3);
    __nv_bfloat16 l0 = __float2bfloat16(v.x - __bfloat162float(h0));
    __nv_bfloat16 l1 = __float2bfloat16(v.y - __bfloat162float(h1));
    __nv_bfloat16 l2 = __float2bfloat16(v.z - __bfloat162float(h2));
    __nv_bfloat16 l3 = __float2bfloat16(v.w - __bfloat162float(h3));
    *(__nv_bfloat162*)(lo + i)     = __halves2bfloat162(l0, l1);
    *(__nv_bfloat162*)(lo + i + 2) = __halves2bfloat162(l2, l3);
}

// W [K,N] fp32 -> Wt [N,K] bf16 hi/lo (transpose + split)
__global__ __launch_bounds__(256)
void conv_wt(const float* __restrict__ W, __nv_bfloat16* __restrict__ Thi,
             __nv_bfloat16* __restrict__ Tlo)
{
    __shared__ float t[32][33];
    int n0 = blockIdx.x * 32, k0 = blockIdx.y * 32;
    int tx = threadIdx.x & 31, ty = threadIdx.x >> 5;
    for (int r = ty; r < 32; r += 8)
        t[r][tx] = W[(size_t)(k0 + r) * Nd + n0 + tx];
    __syncthreads();
    for (int r = ty; r < 32; r += 8) {
        float x = t[tx][r];
        __nv_bfloat16 h = __float2bfloat16(x);
        Thi[(size_t)(n0 + r) * Kd + k0 + tx] = h;
        Tlo[(size_t)(n0 + r) * Kd + k0 + tx] =
            __float2bfloat16(x - __bfloat162float(h));
    }
}

// V [B,S,D] fp32 -> VT [(b*H+h)*DH + d][s] bf16 hi/lo (per-head transpose+split)
__global__ __launch_bounds__(256)
void conv_vt(const float* __restrict__ V, __nv_bfloat16* __restrict__ Thi,
             __nv_bfloat16* __restrict__ Tlo)
{
    __shared__ float t[32][33];
    int s0 = blockIdx.x * 32;
    int r0 = blockIdx.y * 32;
    int bh = r0 >> 7;
    int d0 = r0 & 127;
    int b = bh >> 4, h = bh & 15;
    int tx = threadIdx.x & 31, ty = threadIdx.x >> 5;
    const float* src = V + (size_t)b * S_ * D_ + h * DH_ + d0;
    for (int r = ty; r < 32; r += 8)
        t[r][tx] = src[(size_t)(s0 + r) * D_ + tx];
    __syncthreads();
    for (int r = ty; r < 32; r += 8) {
        float x = t[tx][r];
        __nv_bfloat16 hh = __float2bfloat16(x);
        size_t o = (size_t)(r0 + r) * S_ + s0 + tx;
        Thi[o] = hh;
        Tlo[o] = __float2bfloat16(x - __bfloat162float(hh));
    }
}

// ============================================================================
// HMMA bf16x3 GEMM (validated round 4)
// ============================================================================
constexpr int GM_BM = 128, GM_BN = 128, GM_BK = 64;
constexpr int OFF_AHI = 0, OFF_ALO = 16384, OFF_BHI = 32768, OFF_BLO = 49152;
constexpr int STG_SZ = 65536;
constexpr int GM_SMEM = 1024 + 2 * STG_SZ + 64;

DEV_INLINE uint32_t tile_off(int r, int c) {
    return (uint32_t)(r * 128 + ((c ^ (r & 7)) << 4));
}
// 128-row x 256B logical tile as two stacked 16KB SW128 subtiles, chunk c 0..15
DEV_INLINE uint32_t tileKs(int r, int c) {
    return (uint32_t)((c >> 3) * 16384) + tile_off(r, c & 7);
}

__global__ __launch_bounds__(256, 1)
void hgemm_bf16x3(const __grid_constant__ CUtensorMap mAhi,
                  const __grid_constant__ CUtensorMap mAlo,
                  const __grid_constant__ CUtensorMap mBhi,
                  const __grid_constant__ CUtensorMap mBlo,
                  const float* __restrict__ bias, float* __restrict__ C)
{
    extern __shared__ char smraw[];
    uint32_t smb = (s2u(smraw) + 1023u) & ~1023u;
    const uint32_t full0 = smb + 2 * STG_SZ;
    const uint32_t full1 = full0 + 8;

    const int tid = threadIdx.x;
    const int wid = tid >> 5, lane = tid & 31;
    const int m0 = blockIdx.y * GM_BM;
    const int n0 = blockIdx.x * GM_BN;
    const int warp_m = (wid & 3) * 32;
    const int warp_n = (wid >> 2) * 64;

    if (tid == 0) {
        mbar_init(full0, 1);
        mbar_init(full1, 1);
        fence_mbar_init();
    }
    __syncthreads();

    const int mat = lane >> 3, l7 = lane & 7;
    const int hbA = mat >> 1;
    const int rA = ((mat & 1) << 3) + l7;
    const int hbB = mat & 1;
    const int rB = ((mat >> 1) << 3) + l7;

    float acc[2][8][4];
#pragma unroll
    for (int i = 0; i < 2; i++)
#pragma unroll
        for (int j = 0; j < 8; j++)
#pragma unroll
            for (int q = 0; q < 4; q++) acc[i][j][q] = 0.f;

    if (tid == 0) {
        mbar_expect_tx(full0, 4 * 16384);
        tma2d(smb + OFF_AHI, &mAhi, 0, m0, full0);
        tma2d(smb + OFF_ALO, &mAlo, 0, m0, full0);
        tma2d(smb + OFF_BHI, &mBhi, 0, n0, full0);
        tma2d(smb + OFF_BLO, &mBlo, 0, n0, full0);
    }

    const int NCH = Kd / GM_BK;
    for (int c = 0; c < NCH; c++) {
        const int s = c & 1;
        const uint32_t sb = smb + s * STG_SZ;
        mbar_wait(s == 0 ? full0 : full1, (c >> 1) & 1);
        if (tid == 0 && c + 1 < NCH) {
            const uint32_t sb2 = smb + (s ^ 1) * STG_SZ;
            const uint32_t fb2 = (s == 0) ? full1 : full0;
            mbar_expect_tx(fb2, 4 * 16384);
            int kx = (c + 1) * GM_BK;
            tma2d(sb2 + OFF_AHI, &mAhi, kx, m0, fb2);
            tma2d(sb2 + OFF_ALO, &mAlo, kx, m0, fb2);
            tma2d(sb2 + OFF_BHI, &mBhi, kx, n0, fb2);
            tma2d(sb2 + OFF_BLO, &mBlo, kx, n0, fb2);
        }

#pragma unroll
        for (int ks = 0; ks < 4; ks++) {
            uint32_t ah[2][4], al[2][4], bh[4][4], bl[4][4];
#pragma unroll
            for (int im = 0; im < 2; im++) {
                int row = warp_m + im * 16 + rA;
                int ch = ks * 2 + hbA;
                ldsm4(ah[im], sb + OFF_AHI + tile_off(row, ch));
                ldsm4(al[im], sb + OFF_ALO + tile_off(row, ch));
            }
#pragma unroll
            for (int p = 0; p < 4; p++) {
                int row = warp_n + p * 16 + rB;
                int ch = ks * 2 + hbB;
                ldsm4(bh[p], sb + OFF_BHI + tile_off(row, ch));
                ldsm4(bl[p], sb + OFF_BLO + tile_off(row, ch));
            }
#pragma unroll
            for (int im = 0; im < 2; im++)
#pragma unroll
                for (int p = 0; p < 4; p++) {
                    mma16816(acc[im][2 * p],     ah[im], bh[p][0], bh[p][1]);
                    mma16816(acc[im][2 * p],     ah[im], bl[p][0], bl[p][1]);
                    mma16816(acc[im][2 * p],     al[im], bh[p][0], bh[p][1]);
                    mma16816(acc[im][2 * p + 1], ah[im], bh[p][2], bh[p][3]);
                    mma16816(acc[im][2 * p + 1], ah[im], bl[p][2], bl[p][3]);
                    mma16816(acc[im][2 * p + 1], al[im], bh[p][2], bh[p][3]);
                }
        }
        __syncthreads();
    }

    const int rowg = lane >> 2, colg = (lane & 3) * 2;
#pragma unroll
    for (int im = 0; im < 2; im++) {
#pragma unroll
        for (int jn = 0; jn < 8; jn++) {
            int n = n0 + warp_n + jn * 8 + colg;
            float2 bv = *(const float2*)(bias + n);
            size_t r0 = (size_t)(m0 + warp_m + im * 16 + rowg) * Nd + n;
            float2 v0 = {acc[im][jn][0] + bv.x, acc[im][jn][1] + bv.y};
            *(float2*)(C + r0) = v0;
            float2 v1 = {acc[im][jn][2] + bv.x, acc[im][jn][3] + bv.y};
            *(float2*)(C + r0 + 8 * Nd) = v1;
        }
    }
}

// ============================================================================
// Suffix-sum of V per (b,h)
// ============================================================================
__global__ __launch_bounds__(128)
void v_chunk_sum(const float* __restrict__ V, float* __restrict__ cs)
{
    int idx = blockIdx.x;
    int c = idx & 31;
    int h = (idx >> 5) & 15;
    int b = idx >> 9;
    int d = threadIdx.x;
    size_t base = ((size_t)b * S_ + c * 64) * D_ + h * DH_ + d;
    float s = 0.f;
    for (int r = 0; r < 64; r++) s += V[base + (size_t)r * D_];
    cs[(size_t)idx * DH_ + d] = s;
}

__global__ __launch_bounds__(128)
void v_suffix(const float* __restrict__ V, const float* __restrict__ cs,
              float* __restrict__ Suf)
{
    int idx = blockIdx.x;
    int c = idx & 31;
    int h = (idx >> 5) & 15;
    int b = idx >> 9;
    int d = threadIdx.x;
    int bh = idx >> 5;
    float acc = 0.f;
    for (int c2 = c + 1; c2 < 32; c2++) acc += cs[((size_t)bh * 32 + c2) * DH_ + d];
    size_t base = ((size_t)b * S_ + c * 64) * D_ + h * DH_ + d;
    for (int r = 63; r >= 0; r--) {
        Suf[base + (size_t)r * D_] = acc;
        acc += V[base + (size_t)r * D_];
    }
}

// ============================================================================
// Flash attention v4: log2-domain softmax on MUFU, double-buffered fast path.
// Fast path (qt<15): single-bf16 QK/PV, K/V tiles double-buffered via cp.async.
// Precise path (qt==15): bf16x3, single-buffered. Full-row stats, mask gates PV.
// ============================================================================
constexpr int FT_SMEM = 6 * 32768;
// fast-path slots
constexpr int XFQ = 0, XFK0 = 32768, XFK1 = 65536, XFV0 = 98304, XFV1 = 131072;
// precise-path slots
constexpr int PQHI = 0, PQLO = 32768, PKHI = 65536, PKLO = 98304,
              PVHI = 131072, PVLO = 163840;

DEV_INLINE void softmax_step(float (&acc)[16][4], float (&O)[16][4],
                             float& m0, float& m1, float& l0, float& l1,
                             bool diag, int lrow0, int lrow1, int colq)
{
    float mx0 = -3.0e38f, mx1 = -3.0e38f;
#pragma unroll
    for (int j = 0; j < 16; j++) {
        mx0 = fmaxf(mx0, fmaxf(acc[j][0], acc[j][1]));
        mx1 = fmaxf(mx1, fmaxf(acc[j][2], acc[j][3]));
    }
    mx0 = fmaxf(mx0, __shfl_xor_sync(0xFFFFFFFF, mx0, 1));
    mx0 = fmaxf(mx0, __shfl_xor_sync(0xFFFFFFFF, mx0, 2));
    mx1 = fmaxf(mx1, __shfl_xor_sync(0xFFFFFFFF, mx1, 1));
    mx1 = fmaxf(mx1, __shfl_xor_sync(0xFFFFFFFF, mx1, 2));
    float nm0 = fmaxf(m0, mx0), nm1 = fmaxf(m1, mx1);
    float r0 = ex2f(m0 - nm0), r1 = ex2f(m1 - nm1);
    m0 = nm0; m1 = nm1;
    float s0 = 0.f, s1 = 0.f;
#pragma unroll
    for (int j = 0; j < 16; j++) {
        int col = j * 8 + colq;
        float e0 = ex2f(acc[j][0] - nm0);
        float e1 = ex2f(acc[j][1] - nm0);
        float e2 = ex2f(acc[j][2] - nm1);
        float e3 = ex2f(acc[j][3] - nm1);
        s0 += e0 + e1; s1 += e2 + e3;
        if (diag) {
            if (col     > lrow0) e0 = 0.f;
            if (col + 1 > lrow0) e1 = 0.f;
            if (col     > lrow1) e2 = 0.f;
            if (col + 1 > lrow1) e3 = 0.f;
        }
        acc[j][0] = e0; acc[j][1] = e1; acc[j][2] = e2; acc[j][3] = e3;
    }
    s0 += __shfl_xor_sync(0xFFFFFFFF, s0, 1);
    s0 += __shfl_xor_sync(0xFFFFFFFF, s0, 2);
    s1 += __shfl_xor_sync(0xFFFFFFFF, s1, 1);
    s1 += __shfl_xor_sync(0xFFFFFFFF, s1, 2);
    l0 = l0 * r0 + s0;
    l1 = l1 * r1 + s1;
#pragma unroll
    for (int j = 0; j < 16; j++) {
        O[j][0] *= r0; O[j][1] *= r0; O[j][2] *= r1; O[j][3] *= r1;
    }
}

__global__ __launch_bounds__(256, 1)
void flash_mma(const float* __restrict__ Qp,
               const __nv_bfloat16* __restrict__ Khi,
               const __nv_bfloat16* __restrict__ Klo,
               const __nv_bfloat16* __restrict__ VThi,
               const __nv_bfloat16* __restrict__ VTlo,
               const float* __restrict__ Suf,
               __nv_bfloat16* __restrict__ ctx_hi,
               __nv_bfloat16* __restrict__ ctx_lo)
{
    extern __shared__ char fsm[];
    const uint32_t smb = s2u(fsm);
    const int tid = threadIdx.x, wid = tid >> 5, lane = tid & 31;
    const int bh = blockIdx.x, qt = blockIdx.y;
    const int b = bh >> 4, h = bh & 15;
    const size_t base = (size_t)b * S_ * D_ + h * DH_;
    const int q0 = qt * 128;
    const bool precise = (qt == 15);

    const int mat = lane >> 3, l7 = lane & 7;
    const int hbA = mat >> 1, rA = ((mat & 1) << 3) + l7;
    const int hbB = mat & 1, rB = ((mat >> 1) << 3) + l7;
    const int rowg = lane >> 2, colq = (lane & 3) * 2;
    const int warp_m = wid * 16;
    const int lrow0 = warp_m + rowg, lrow1 = lrow0 + 8;

    // ---- load Q tile once: scaled by SCL2 (softmax moves to log2 domain) ----
#pragma unroll
    for (int i = 0; i < 16; i++) {
        int idx = i * 256 + tid;
        int r = idx >> 5, c4 = (idx & 31) * 4;
        float4 v = *(const float4*)(Qp + base + (size_t)(q0 + r) * D_ + c4);
        v.x *= SCL2; v.y *= SCL2; v.z *= SCL2; v.w *= SCL2;
        uint32_t off = tileKs(r, c4 >> 3) + (c4 & 4) * 2;
        *(uint2*)(fsm + XFQ + off) = make_uint2(pack_bf2(v.x, v.y), pack_bf2(v.z, v.w));
        if (precise) {
            float hx = __bfloat162float(__float2bfloat16(v.x));
            float hy = __bfloat162float(__float2bfloat16(v.y));
            float hz = __bfloat162float(__float2bfloat16(v.z));
            float hw = __bfloat162float(__float2bfloat16(v.w));
            *(uint2*)(fsm + PQLO + off) =
                make_uint2(pack_bf2(v.x - hx, v.y - hy), pack_bf2(v.z - hz, v.w - hw));
        }
    }

    float O[16][4];
#pragma unroll
    for (int j = 0; j < 16; j++)
#pragma unroll
        for (int q = 0; q < 4; q++) O[j][q] = 0.f;
    float m0 = -3.0e38f, m1 = -3.0e38f, l0 = 0.f, l1 = 0.f;

    const __nv_bfloat16* Kh_b = Khi + base;                    // row stride D_
    const __nv_bfloat16* Kl_b = Klo + base;
    const __nv_bfloat16* Vh_b = VThi + (size_t)bh * DH_ * S_;  // row stride S_
    const __nv_bfloat16* Vl_b = VTlo + (size_t)bh * DH_ * S_;

    if (!precise) {
        // ================= FAST PATH: pipelined single-bf16 =================
        auto loadkv = [&](int kt2, uint32_t kb, uint32_t vb) {
            int kk0 = kt2 * 128;
#pragma unroll
            for (int i = 0; i < 8; i++) {
                int idx = i * 256 + tid;
                int r = idx >> 4, c = idx & 15;
                uint32_t so = tileKs(r, c);
                cpa16(smb + kb + so, Kh_b + (size_t)(kk0 + r) * D_ + c * 8);
                cpa16(smb + vb + so, Vh_b + (size_t)r * S_ + kk0 + c * 8);
            }
        };
        loadkv(0, XFK0, XFV0);
        CP_COMMIT();

        for (int kt = 0; kt < 16; kt++) {
            const uint32_t kb = (kt & 1) ? XFK1 : XFK0;
            const uint32_t vb = (kt & 1) ? XFV1 : XFV0;
            if (kt < 15) {
                loadkv(kt + 1, (kt & 1) ? XFK0 : XFK1, (kt & 1) ? XFV0 : XFV1);
                CP_COMMIT();
                cp_wait1();
            } else {
                cp_wait0();
            }
            __syncthreads();

            // S' = (Q*SCL2) K^T   (log2-domain scores)
            float acc[16][4];
#pragma unroll
            for (int j = 0; j < 16; j++)
#pragma unroll
                for (int q = 0; q < 4; q++) acc[j][q] = 0.f;
#pragma unroll
            for (int ks = 0; ks < 8; ks++) {
                uint32_t ah[4];
                ldsm4(ah, smb + XFQ + tileKs(warp_m + rA, ks * 2 + hbA));
#pragma unroll
                for (int p = 0; p < 8; p++) {
                    uint32_t bhf[4];
                    ldsm4(bhf, smb + kb + tileKs(p * 16 + rB, ks * 2 + hbB));
                    mma16816(acc[2 * p],     ah, bhf[0], bhf[1]);
                    mma16816(acc[2 * p + 1], ah, bhf[2], bhf[3]);
                }
            }

            softmax_step(acc, O, m0, m1, l0, l1, kt == qt, lrow0, lrow1, colq);

            if (kt <= qt) {
#pragma unroll
                for (int ks = 0; ks < 8; ks++) {
                    uint32_t pah[4];
                    pah[0] = pack_bf2(acc[2 * ks][0], acc[2 * ks][1]);
                    pah[1] = pack_bf2(acc[2 * ks][2], acc[2 * ks][3]);
                    pah[2] = pack_bf2(acc[2 * ks + 1][0], acc[2 * ks + 1][1]);
                    pah[3] = pack_bf2(acc[2 * ks + 1][2], acc[2 * ks + 1][3]);
#pragma unroll
                    for (int pn = 0; pn < 8; pn++) {
                        uint32_t vh[4];
                        ldsm4(vh, smb + vb + tileKs(pn * 16 + rB, ks * 2 + hbB));
                        mma16816(O[2 * pn],     pah, vh[0], vh[1]);
                        mma16816(O[2 * pn + 1], pah, vh[2], vh[3]);
                    }
                }
            }
            __syncthreads();
        }
    } else {
        // ================= PRECISE PATH (qt==15): bf16x3 ====================
        for (int kt = 0; kt < 16; kt++) {
            const int k0 = kt * 128;
            __syncthreads();
#pragma unroll
            for (int i = 0; i < 8; i++) {
                int idx = i * 256 + tid;
                int r = idx >> 4, c = idx & 15;
                uint32_t so = tileKs(r, c);
                cpa16(smb + PKHI + so, Kh_b + (size_t)(k0 + r) * D_ + c * 8);
                cpa16(smb + PVHI + so, Vh_b + (size_t)r * S_ + k0 + c * 8);
                cpa16(smb + PKLO + so, Kl_b + (size_t)(k0 + r) * D_ + c * 8);
                cpa16(smb + PVLO + so, Vl_b + (size_t)r * S_ + k0 + c * 8);
            }
            CP_COMMIT();
            cp_wait0();
            __syncthreads();

            float acc[16][4];
#pragma unroll
            for (int j = 0; j < 16; j++)
#pragma unroll
                for (int q = 0; q < 4; q++) acc[j][q] = 0.f;
#pragma unroll
            for (int ks = 0; ks < 8; ks++) {
                uint32_t ah[4], al[4];
                ldsm4(ah, smb + PQHI + tileKs(warp_m + rA, ks * 2 + hbA));
                ldsm4(al, smb + PQLO + tileKs(warp_m + rA, ks * 2 + hbA));
#pragma unroll
                for (int p = 0; p < 8; p++) {
                    uint32_t bhf[4], blf[4];
                    int brow = p * 16 + rB, bch = ks * 2 + hbB;
                    ldsm4(bhf, smb + PKHI + tileKs(brow, bch));
                    ldsm4(blf, smb + PKLO + tileKs(brow, bch));
                    mma16816(acc[2 * p],     ah, bhf[0], bhf[1]);
                    mma16816(acc[2 * p],     al, bhf[0], bhf[1]);
                    mma16816(acc[2 * p],     ah, blf[0], blf[1]);
                    mma16816(acc[2 * p + 1], ah, bhf[2], bhf[3]);
                    mma16816(acc[2 * p + 1], al, bhf[2], bhf[3]);
                    mma16816(acc[2 * p + 1], ah, blf[2], blf[3]);
                }
            }

            softmax_step(acc, O, m0, m1, l0, l1, kt == qt, lrow0, lrow1, colq);

            {
#pragma unroll
                for (int ks = 0; ks < 8; ks++) {
                    uint32_t pah[4], pal[4];
                    float x0 = acc[2 * ks][0], x1 = acc[2 * ks][1];
                    float x2 = acc[2 * ks][2], x3 = acc[2 * ks][3];
                    float y0 = acc[2 * ks + 1][0], y1 = acc[2 * ks + 1][1];
                    float y2 = acc[2 * ks + 1][2], y3 = acc[2 * ks + 1][3];
                    pah[0] = pack_bf2(x0, x1);
                    pah[1] = pack_bf2(x2, x3);
                    pah[2] = pack_bf2(y0, y1);
                    pah[3] = pack_bf2(y2, y3);
                    float hx0 = __bfloat162float(__float2bfloat16(x0));
                    float hx1 = __bfloat162float(__float2bfloat16(x1));
                    float hx2 = __bfloat162float(__float2bfloat16(x2));
                    float hx3 = __bfloat162float(__float2bfloat16(x3));
                    float hy0 = __bfloat162float(__float2bfloat16(y0));
                    float hy1 = __bfloat162float(__float2bfloat16(y1));
                    float hy2 = __bfloat162float(__float2bfloat16(y2));
                    float hy3 = __bfloat162float(__float2bfloat16(y3));
                    pal[0] = pack_bf2(x0 - hx0, x1 - hx1);
                    pal[1] = pack_bf2(x2 - hx2, x3 - hx3);
                    pal[2] = pack_bf2(y0 - hy0, y1 - hy1);
                    pal[3] = pack_bf2(y2 - hy2, y3 - hy3);
#pragma unroll
                    for (int pn = 0; pn < 8; pn++) {
                        uint32_t vh[4], vl[4];
                        int brow = pn * 16 + rB, bch = ks * 2 + hbB;
                        ldsm4(vh, smb + PVHI + tileKs(brow, bch));
                        ldsm4(vl, smb + PVLO + tileKs(brow, bch));
                        mma16816(O[2 * pn],     pah, vh[0], vh[1]);
                        mma16816(O[2 * pn],     pal, vh[0], vh[1]);
                        mma16816(O[2 * pn],     pah, vl[0], vl[1]);
                        mma16816(O[2 * pn + 1], pah, vh[2], vh[3]);
                        mma16816(O[2 * pn + 1], pal, vh[2], vh[3]);
                        mma16816(O[2 * pn + 1], pah, vl[2], vl[3]);
                    }
                }
            }
        }
    }

    // ---- epilogue: w = O/l - 1e9*Suf, write bf16 hi/lo splits ----
    const float inv0 = 1.f / l0, inv1 = 1.f / l1;
    const int grow0 = q0 + warp_m + rowg;
#pragma unroll
    for (int j = 0; j < 16; j++) {
        int d = j * 8 + colq;
        size_t o0 = base + (size_t)grow0 * D_ + d;
        size_t o1 = o0 + 8 * (size_t)D_;
        float2 sf0 = *(const float2*)(Suf + o0);
        float2 sf1 = *(const float2*)(Suf + o1);
        float w0x = fmaf(-1.0e9f, sf0.x, O[j][0] * inv0);
        float w0y = fmaf(-1.0e9f, sf0.y, O[j][1] * inv0);
        float w1x = fmaf(-1.0e9f, sf1.x, O[j][2] * inv1);
        float w1y = fmaf(-1.0e9f, sf1.y, O[j][3] * inv1);
        *(uint32_t*)(ctx_hi + o0) = pack_bf2(w0x, w0y);
        *(uint32_t*)(ctx_hi + o1) = pack_bf2(w1x, w1y);
        float h0x = __bfloat162float(__float2bfloat16(w0x));
        float h0y = __bfloat162float(__float2bfloat16(w0y));
        float h1x = __bfloat162float(__float2bfloat16(w1x));
        float h1y = __bfloat162float(__float2bfloat16(w1y));
        *(uint32_t*)(ctx_lo + o0) = pack_bf2(w0x - h0x, w0y - h0y);
        *(uint32_t*)(ctx_lo + o1) = pack_bf2(w1x - h1x, w1y - h1y);
    }
}

// ============================================================================
typedef CUresult (*PFN_encodeTiled)(
    CUtensorMap*, CUtensorMapDataType, cuuint32_t, void*,
    const cuuint64_t*, const cuuint64_t*, const cuuint32_t*, const cuuint32_t*,
    CUtensorMapInterleave, CUtensorMapSwizzle, CUtensorMapL2promotion,
    CUtensorMapFloatOOBfill);

static void make_map_bf16(PFN_encodeTiled enc, CUtensorMap* m, void* ptr,
                          unsigned long long rows)
{
    cuuint64_t dims[2] = {(cuuint64_t)Kd, (cuuint64_t)rows};
    cuuint64_t strides[1] = {(cuuint64_t)Kd * 2};
    cuuint32_t box[2] = {64, 128};
    cuuint32_t es[2] = {1, 1};
    enc(m, CU_TENSOR_MAP_DATA_TYPE_BFLOAT16, 2, ptr, dims, strides, box, es,
        CU_TENSOR_MAP_INTERLEAVE_NONE, CU_TENSOR_MAP_SWIZZLE_128B,
        CU_TENSOR_MAP_L2_PROMOTION_L2_128B, CU_TENSOR_MAP_FLOAT_OOB_FILL_NONE);
}

extern "C" void kernel_launch(void* const* d_in, const int* in_sizes, int n_in,
                              void* d_out, int out_size)
{
    const float* q  = (const float*)d_in[0];
    const float* k  = (const float*)d_in[1];
    const float* v  = (const float*)d_in[2];
    const float* Wq = (const float*)d_in[3];
    const float* bq = (const float*)d_in[4];
    const float* Wk = (const float*)d_in[5];
    const float* bk = (const float*)d_in[6];
    const float* Wv = (const float*)d_in[7];
    const float* bvv = (const float*)d_in[8];
    const float* Wo = (const float*)d_in[9];
    const float* bo = (const float*)d_in[10];
    float* out = (float*)d_out;
    (void)in_sizes; (void)n_in; (void)out_size;

    float *gQ, *gK, *gV, *gSuf, *gcs;
    cudaGetSymbolAddress((void**)&gQ,   g_Q);
    cudaGetSymbolAddress((void**)&gK,   g_K);
    cudaGetSymbolAddress((void**)&gV,   g_V);
    cudaGetSymbolAddress((void**)&gSuf, g_Suf);
    cudaGetSymbolAddress((void**)&gcs,  g_csum);
    __nv_bfloat16 *gAhi, *gAlo, *gWthi, *gWtlo, *gKhi, *gKlo, *gVThi, *gVTlo;
    cudaGetSymbolAddress((void**)&gAhi, g_Ahi);
    cudaGetSymbolAddress((void**)&gAlo, g_Alo);
    cudaGetSymbolAddress((void**)&gWthi, g_Wthi);
    cudaGetSymbolAddress((void**)&gWtlo, g_Wtlo);
    cudaGetSymbolAddress((void**)&gKhi, g_Khi);
    cudaGetSymbolAddress((void**)&gKlo, g_Klo);
    cudaGetSymbolAddress((void**)&gVThi, g_VThi);
    cudaGetSymbolAddress((void**)&gVTlo, g_VTlo);

    void* pfn = nullptr;
    cudaDriverEntryPointQueryResult qr;
    cudaGetDriverEntryPointByVersion("cuTensorMapEncodeTiled", &pfn, 12000,
                                     cudaEnableDefault, &qr);
    PFN_encodeTiled enc = (PFN_encodeTiled)pfn;

    const int WN = D_ * D_;
    CUtensorMap mAhi, mAlo;
    CUtensorMap mWhi[4], mWlo[4];
    make_map_bf16(enc, &mAhi, gAhi, M_);
    make_map_bf16(enc, &mAlo, gAlo, M_);
    for (int i = 0; i < 4; i++) {
        make_map_bf16(enc, &mWhi[i], gWthi + (size_t)i * WN, Nd);
        make_map_bf16(enc, &mWlo[i], gWtlo + (size_t)i * WN, Nd);
    }

    cudaFuncSetAttribute(flash_mma, cudaFuncAttributeMaxDynamicSharedMemorySize,
                         FT_SMEM);
    cudaFuncSetAttribute(hgemm_bf16x3, cudaFuncAttributeMaxDynamicSharedMemorySize,
                         GM_SMEM);

    dim3 wg(64, 64);
    conv_wt<<<wg, 256>>>(Wq, gWthi + 0 * (size_t)WN, gWtlo + 0 * (size_t)WN);
    conv_wt<<<wg, 256>>>(Wk, gWthi + 1 * (size_t)WN, gWtlo + 1 * (size_t)WN);
    conv_wt<<<wg, 256>>>(Wv, gWthi + 2 * (size_t)WN, gWtlo + 2 * (size_t)WN);
    conv_wt<<<wg, 256>>>(Wo, gWthi + 3 * (size_t)WN, gWtlo + 3 * (size_t)WN);

    dim3 gg(Nd / GM_BN, M_ / GM_BM);  // (16, 64)
    const int NCV = M_ * D_ / 4 / 256;

    conv_split<<<NCV, 256>>>(q, gAhi, gAlo, M_ * D_);
    hgemm_bf16x3<<<gg, 256, GM_SMEM>>>(mAhi, mAlo, mWhi[0], mWlo[0], bq, gQ);
    conv_split<<<NCV, 256>>>(k, gAhi, gAlo, M_ * D_);
    hgemm_bf16x3<<<gg, 256, GM_SMEM>>>(mAhi, mAlo, mWhi[1], mWlo[1], bk, gK);
    conv_split<<<NCV, 256>>>(v, gAhi, gAlo, M_ * D_);
    hgemm_bf16x3<<<gg, 256, GM_SMEM>>>(mAhi, mAlo, mWhi[2], mWlo[2], bvv, gV);

    // pre-split K and transposed V for flash
    conv_split<<<NCV, 256>>>(gK, gKhi, gKlo, M_ * D_);
    conv_vt<<<dim3(S_ / 32, M_ / 32), 256>>>(gV, gVThi, gVTlo);

    v_chunk_sum<<<Bb_ * H_ * 32, 128>>>(gV, gcs);
    v_suffix<<<Bb_ * H_ * 32, 128>>>(gV, gcs, gSuf);
    flash_mma<<<dim3(Bb_ * H_, 16), 256, FT_SMEM>>>(gQ, gKhi, gKlo, gVThi, gVTlo,
                                                    gSuf, gAhi, gAlo);

    hgemm_bf16x3<<<gg, 256, GM_SMEM>>>(mAhi, mAlo, mWhi[3], mWlo[3], bo, out);
}